// round 1
// baseline (speedup 1.0000x reference)
#include <cuda_runtime.h>
#include <math.h>

#define BATCH 256
#define SEQ   512
#define DIM   512

// Scratch (allocation-free rule: __device__ globals). 4 x 268 MB.
static __device__ float g_q  [ (size_t)BATCH*SEQ*DIM ];
static __device__ float g_p  [ (size_t)BATCH*SEQ*SEQ ];
static __device__ float g_mix[ (size_t)BATCH*SEQ*DIM ];
static __device__ float g_h  [ (size_t)BATCH*SEQ*DIM ];

// ---------------------------------------------------------------------------
// Generic 128x128x8 SGEMM, 256 threads, 8x8 per thread.
//   C[m,n] = sum_k A[m,k] * (TRANS_B ? B[n,k] : B[k,n])   (+ optional 2nd pair)
// All of M, N(=128*gridDim.x), K are multiples of 128/8 here -> no guards.
// DUAL: accumulate a second (A2,B2) pair over the same K (handles concat).
// TANH: apply tanhf in epilogue.
// ---------------------------------------------------------------------------
template<bool TRANS_B, bool DUAL, bool TANH>
__global__ void __launch_bounds__(256)
gemm_kernel(const float* __restrict__ A, const float* __restrict__ A2, int lda,
            const float* __restrict__ B, const float* __restrict__ B2, int ldb,
            float* __restrict__ C, int ldc, int K,
            long sA, long sB, long sC)
{
    __shared__ float As[8][128];
    __shared__ float Bs[8][128];

    const int  b    = blockIdx.z;
    const long rowA = (long)blockIdx.y * 128;
    const int  colB = blockIdx.x * 128;
    const int  tid  = threadIdx.x;
    const int  ty   = tid >> 4;
    const int  tx   = tid & 15;
    const int  mB   = ty * 8;
    const int  nB   = tx * 8;

    float acc[8][8];
#pragma unroll
    for (int i = 0; i < 8; ++i)
#pragma unroll
        for (int j = 0; j < 8; ++j) acc[i][j] = 0.f;

    const int ar = tid >> 1, ac = (tid & 1) * 4;      // A tile: 128 rows x 8 k
    const int br = tid >> 5, bc = (tid & 31) * 4;     // B (NN): 8 rows x 128 n

    const int passes = DUAL ? 2 : 1;
    for (int pass = 0; pass < passes; ++pass) {
        const float* Ap = ((DUAL && pass) ? A2 : A) + (long)b * sA;
        const float* Bp = ((DUAL && pass) ? B2 : B) + (long)b * sB;

        for (int k0 = 0; k0 < K; k0 += 8) {
            float4 av = *(const float4*)(Ap + (rowA + ar) * (long)lda + k0 + ac);
            As[ac + 0][ar] = av.x; As[ac + 1][ar] = av.y;
            As[ac + 2][ar] = av.z; As[ac + 3][ar] = av.w;

            if (TRANS_B) {
                float4 bv = *(const float4*)(Bp + (long)(colB + ar) * ldb + k0 + ac);
                Bs[ac + 0][ar] = bv.x; Bs[ac + 1][ar] = bv.y;
                Bs[ac + 2][ar] = bv.z; Bs[ac + 3][ar] = bv.w;
            } else {
                float4 bv = *(const float4*)(Bp + (long)(k0 + br) * ldb + colB + bc);
                *(float4*)&Bs[br][bc] = bv;
            }
            __syncthreads();

#pragma unroll
            for (int k = 0; k < 8; ++k) {
                float4 a0 = *(const float4*)&As[k][mB];
                float4 a1 = *(const float4*)&As[k][mB + 4];
                float4 b0 = *(const float4*)&Bs[k][nB];
                float4 b1 = *(const float4*)&Bs[k][nB + 4];
                float ar8[8] = {a0.x, a0.y, a0.z, a0.w, a1.x, a1.y, a1.z, a1.w};
                float br8[8] = {b0.x, b0.y, b0.z, b0.w, b1.x, b1.y, b1.z, b1.w};
#pragma unroll
                for (int i = 0; i < 8; ++i)
#pragma unroll
                    for (int j = 0; j < 8; ++j)
                        acc[i][j] += ar8[i] * br8[j];
            }
            __syncthreads();
        }
    }

    float* Cb = C + (long)b * sC;
#pragma unroll
    for (int i = 0; i < 8; ++i) {
        float* cp = Cb + (rowA + mB + i) * (long)ldc + colB + nB;
        float4 v0, v1;
        if (TANH) {
            v0.x = tanhf(acc[i][0]); v0.y = tanhf(acc[i][1]);
            v0.z = tanhf(acc[i][2]); v0.w = tanhf(acc[i][3]);
            v1.x = tanhf(acc[i][4]); v1.y = tanhf(acc[i][5]);
            v1.z = tanhf(acc[i][6]); v1.w = tanhf(acc[i][7]);
        } else {
            v0.x = acc[i][0]; v0.y = acc[i][1]; v0.z = acc[i][2]; v0.w = acc[i][3];
            v1.x = acc[i][4]; v1.y = acc[i][5]; v1.z = acc[i][6]; v1.w = acc[i][7];
        }
        *(float4*)cp       = v0;
        *(float4*)(cp + 4) = v1;
    }
}

// ---------------------------------------------------------------------------
// Row softmax over 512 elements, in place. One block (128 thr) per row.
// ---------------------------------------------------------------------------
__global__ void __launch_bounds__(128)
softmax512_kernel(float* __restrict__ P)
{
    __shared__ float redm[4];
    __shared__ float reds[4];

    float* p = P + (long)blockIdx.x * 512;
    const int t = threadIdx.x;

    float4 v = ((float4*)p)[t];
    float m = fmaxf(fmaxf(v.x, v.y), fmaxf(v.z, v.w));
#pragma unroll
    for (int o = 16; o; o >>= 1) m = fmaxf(m, __shfl_xor_sync(0xffffffffu, m, o));
    if ((t & 31) == 0) redm[t >> 5] = m;
    __syncthreads();
    m = fmaxf(fmaxf(redm[0], redm[1]), fmaxf(redm[2], redm[3]));

    v.x = __expf(v.x - m); v.y = __expf(v.y - m);
    v.z = __expf(v.z - m); v.w = __expf(v.w - m);
    float s = v.x + v.y + v.z + v.w;
#pragma unroll
    for (int o = 16; o; o >>= 1) s += __shfl_xor_sync(0xffffffffu, s, o);
    if ((t & 31) == 0) reds[t >> 5] = s;
    __syncthreads();
    s = reds[0] + reds[1] + reds[2] + reds[3];

    float r = 1.0f / s;
    v.x *= r; v.y *= r; v.z *= r; v.w *= r;
    ((float4*)p)[t] = v;
}

// ---------------------------------------------------------------------------
// Mean over L: out[n,d] = (1/512) * sum_l H[n,l,d]
// ---------------------------------------------------------------------------
__global__ void __launch_bounds__(256)
pool_kernel(const float* __restrict__ H, float* __restrict__ out)
{
    const int idx = blockIdx.x * blockDim.x + threadIdx.x;   // n*DIM + d
    const int n = idx >> 9;
    const int d = idx & 511;
    const float* h = H + (long)n * SEQ * DIM + d;
    float s = 0.f;
#pragma unroll 8
    for (int l = 0; l < SEQ; ++l) s += h[(long)l * DIM];
    out[idx] = s * (1.0f / SEQ);
}

// ---------------------------------------------------------------------------

static void attention_block(const float* x, const float* Win, const float* Wout,
                            float* q, float* p, float* mix, float* hout, bool do_tanh)
{
    const long LD = (long)SEQ * DIM;
    const long LLs = (long)SEQ * SEQ;

    // q = x @ Win^T        (flattened M = BATCH*SEQ)
    gemm_kernel<true, false, false><<<dim3(DIM / 128, (BATCH * SEQ) / 128, 1), 256>>>(
        x, nullptr, DIM, Win, nullptr, DIM, q, DIM, DIM, 0, 0, 0);

    // S[b] = q[b] @ x[b]^T  (batched over z)
    gemm_kernel<true, false, false><<<dim3(SEQ / 128, SEQ / 128, BATCH), 256>>>(
        q, nullptr, DIM, x, nullptr, DIM, p, SEQ, DIM, LD, LD, LLs);

    // softmax rows
    softmax512_kernel<<<BATCH * SEQ, 128>>>(p);

    // mix[b] = P[b] @ x[b]
    gemm_kernel<false, false, false><<<dim3(DIM / 128, SEQ / 128, BATCH), 256>>>(
        p, nullptr, SEQ, x, nullptr, DIM, mix, DIM, SEQ, LLs, LD, LD);

    // hout = act( mix @ Wout[:, :D]^T + q @ Wout[:, D:]^T )   (flattened M)
    if (do_tanh)
        gemm_kernel<true, true, true><<<dim3(DIM / 128, (BATCH * SEQ) / 128, 1), 256>>>(
            mix, q, DIM, Wout, Wout + DIM, 2 * DIM, hout, DIM, DIM, 0, 0, 0);
    else
        gemm_kernel<true, true, false><<<dim3(DIM / 128, (BATCH * SEQ) / 128, 1), 256>>>(
            mix, q, DIM, Wout, Wout + DIM, 2 * DIM, hout, DIM, DIM, 0, 0, 0);
}

extern "C" void kernel_launch(void* const* d_in, const int* in_sizes, int n_in,
                              void* d_out, int out_size)
{
    const float* x     = (const float*)d_in[0];
    const float* Win1  = (const float*)d_in[1];
    const float* Wout1 = (const float*)d_in[2];
    const float* Win2  = (const float*)d_in[3];
    const float* Wout2 = (const float*)d_in[4];
    float* out = (float*)d_out;

    float *q, *p, *mix, *h;
    cudaGetSymbolAddress((void**)&q,   g_q);
    cudaGetSymbolAddress((void**)&p,   g_p);
    cudaGetSymbolAddress((void**)&mix, g_mix);
    cudaGetSymbolAddress((void**)&h,   g_h);

    // Block 1: x -> h (tanh)
    attention_block(x, Win1, Wout1, q, p, mix, h, true);

    // Block 2: h -> p (no tanh). Its out kernel reads only mix & q, so writing
    // the result into p (L==D, identical extent) is safe.
    attention_block(h, Win2, Wout2, q, p, mix, p, false);

    // Mean over L -> [N, D] == [N, D, 1, 1]
    pool_kernel<<<(BATCH * DIM) / 256, 256>>>(p, out);
}

// round 2
// speedup vs baseline: 1.0008x; 1.0008x over previous
#include <cuda_runtime.h>
#include <math.h>

#define BATCH 256
#define SEQ   512
#define DIM   512

// Scratch (allocation-free rule: __device__ globals). 4 x 268 MB.
static __device__ float g_q  [ (size_t)BATCH*SEQ*DIM ];
static __device__ float g_p  [ (size_t)BATCH*SEQ*SEQ ];
static __device__ float g_mix[ (size_t)BATCH*SEQ*DIM ];
static __device__ float g_h  [ (size_t)BATCH*SEQ*DIM ];

// ---------------------------------------------------------------------------
// Generic 128x128x8 SGEMM, 256 threads, 8x8 per thread.
//   C[m,n] = sum_k A[m,k] * (TRANS_B ? B[n,k] : B[k,n])   (+ optional 2nd pair)
// All of M, N(=128*gridDim.x), K are multiples of 128/8 here -> no guards.
// DUAL: accumulate a second (A2,B2) pair over the same K (handles concat).
// TANH: apply tanhf in epilogue.
// ---------------------------------------------------------------------------
template<bool TRANS_B, bool DUAL, bool TANH>
__global__ void __launch_bounds__(256)
gemm_kernel(const float* __restrict__ A, const float* __restrict__ A2, int lda,
            const float* __restrict__ B, const float* __restrict__ B2, int ldb,
            float* __restrict__ C, int ldc, int K,
            long sA, long sB, long sC)
{
    __shared__ float As[8][128];
    __shared__ float Bs[8][128];

    const int  b    = blockIdx.z;
    const long rowA = (long)blockIdx.y * 128;
    const int  colB = blockIdx.x * 128;
    const int  tid  = threadIdx.x;
    const int  ty   = tid >> 4;
    const int  tx   = tid & 15;
    const int  mB   = ty * 8;
    const int  nB   = tx * 8;

    float acc[8][8];
#pragma unroll
    for (int i = 0; i < 8; ++i)
#pragma unroll
        for (int j = 0; j < 8; ++j) acc[i][j] = 0.f;

    const int ar = tid >> 1, ac = (tid & 1) * 4;      // A tile: 128 rows x 8 k
    const int br = tid >> 5, bc = (tid & 31) * 4;     // B (NN): 8 rows x 128 n

    const int passes = DUAL ? 2 : 1;
    for (int pass = 0; pass < passes; ++pass) {
        const float* Ap = ((DUAL && pass) ? A2 : A) + (long)b * sA;
        const float* Bp = ((DUAL && pass) ? B2 : B) + (long)b * sB;

        for (int k0 = 0; k0 < K; k0 += 8) {
            float4 av = *(const float4*)(Ap + (rowA + ar) * (long)lda + k0 + ac);
            As[ac + 0][ar] = av.x; As[ac + 1][ar] = av.y;
            As[ac + 2][ar] = av.z; As[ac + 3][ar] = av.w;

            if (TRANS_B) {
                float4 bv = *(const float4*)(Bp + (long)(colB + ar) * ldb + k0 + ac);
                Bs[ac + 0][ar] = bv.x; Bs[ac + 1][ar] = bv.y;
                Bs[ac + 2][ar] = bv.z; Bs[ac + 3][ar] = bv.w;
            } else {
                float4 bv = *(const float4*)(Bp + (long)(k0 + br) * ldb + colB + bc);
                *(float4*)&Bs[br][bc] = bv;
            }
            __syncthreads();

#pragma unroll
            for (int k = 0; k < 8; ++k) {
                float4 a0 = *(const float4*)&As[k][mB];
                float4 a1 = *(const float4*)&As[k][mB + 4];
                float4 b0 = *(const float4*)&Bs[k][nB];
                float4 b1 = *(const float4*)&Bs[k][nB + 4];
                float ar8[8] = {a0.x, a0.y, a0.z, a0.w, a1.x, a1.y, a1.z, a1.w};
                float br8[8] = {b0.x, b0.y, b0.z, b0.w, b1.x, b1.y, b1.z, b1.w};
#pragma unroll
                for (int i = 0; i < 8; ++i)
#pragma unroll
                    for (int j = 0; j < 8; ++j)
                        acc[i][j] += ar8[i] * br8[j];
            }
            __syncthreads();
        }
    }

    float* Cb = C + (long)b * sC;
#pragma unroll
    for (int i = 0; i < 8; ++i) {
        float* cp = Cb + (rowA + mB + i) * (long)ldc + colB + nB;
        float4 v0, v1;
        if (TANH) {
            v0.x = tanhf(acc[i][0]); v0.y = tanhf(acc[i][1]);
            v0.z = tanhf(acc[i][2]); v0.w = tanhf(acc[i][3]);
            v1.x = tanhf(acc[i][4]); v1.y = tanhf(acc[i][5]);
            v1.z = tanhf(acc[i][6]); v1.w = tanhf(acc[i][7]);
        } else {
            v0.x = acc[i][0]; v0.y = acc[i][1]; v0.z = acc[i][2]; v0.w = acc[i][3];
            v1.x = acc[i][4]; v1.y = acc[i][5]; v1.z = acc[i][6]; v1.w = acc[i][7];
        }
        *(float4*)cp       = v0;
        *(float4*)(cp + 4) = v1;
    }
}

// ---------------------------------------------------------------------------
// Row softmax over 512 elements, in place. One block (128 thr) per row.
// ---------------------------------------------------------------------------
__global__ void __launch_bounds__(128)
softmax512_kernel(float* __restrict__ P)
{
    __shared__ float redm[4];
    __shared__ float reds[4];

    float* p = P + (long)blockIdx.x * 512;
    const int t = threadIdx.x;

    float4 v = ((float4*)p)[t];
    float m = fmaxf(fmaxf(v.x, v.y), fmaxf(v.z, v.w));
#pragma unroll
    for (int o = 16; o; o >>= 1) m = fmaxf(m, __shfl_xor_sync(0xffffffffu, m, o));
    if ((t & 31) == 0) redm[t >> 5] = m;
    __syncthreads();
    m = fmaxf(fmaxf(redm[0], redm[1]), fmaxf(redm[2], redm[3]));

    v.x = __expf(v.x - m); v.y = __expf(v.y - m);
    v.z = __expf(v.z - m); v.w = __expf(v.w - m);
    float s = v.x + v.y + v.z + v.w;
#pragma unroll
    for (int o = 16; o; o >>= 1) s += __shfl_xor_sync(0xffffffffu, s, o);
    if ((t & 31) == 0) reds[t >> 5] = s;
    __syncthreads();
    s = reds[0] + reds[1] + reds[2] + reds[3];

    float r = 1.0f / s;
    v.x *= r; v.y *= r; v.z *= r; v.w *= r;
    ((float4*)p)[t] = v;
}

// ---------------------------------------------------------------------------
// Mean over L: out[n,d] = (1/512) * sum_l H[n,l,d]
// ---------------------------------------------------------------------------
__global__ void __launch_bounds__(256)
pool_kernel(const float* __restrict__ H, float* __restrict__ out)
{
    const int idx = blockIdx.x * blockDim.x + threadIdx.x;   // n*DIM + d
    const int n = idx >> 9;
    const int d = idx & 511;
    const float* h = H + (long)n * SEQ * DIM + d;
    float s = 0.f;
#pragma unroll 8
    for (int l = 0; l < SEQ; ++l) s += h[(long)l * DIM];
    out[idx] = s * (1.0f / SEQ);
}

// ---------------------------------------------------------------------------

static void attention_block(const float* x, const float* Win, const float* Wout,
                            float* q, float* p, float* mix, float* hout, bool do_tanh)
{
    const long LD = (long)SEQ * DIM;
    const long LLs = (long)SEQ * SEQ;

    // q = x @ Win^T        (flattened M = BATCH*SEQ)
    gemm_kernel<true, false, false><<<dim3(DIM / 128, (BATCH * SEQ) / 128, 1), 256>>>(
        x, nullptr, DIM, Win, nullptr, DIM, q, DIM, DIM, 0, 0, 0);

    // S[b] = q[b] @ x[b]^T  (batched over z)
    gemm_kernel<true, false, false><<<dim3(SEQ / 128, SEQ / 128, BATCH), 256>>>(
        q, nullptr, DIM, x, nullptr, DIM, p, SEQ, DIM, LD, LD, LLs);

    // softmax rows
    softmax512_kernel<<<BATCH * SEQ, 128>>>(p);

    // mix[b] = P[b] @ x[b]
    gemm_kernel<false, false, false><<<dim3(DIM / 128, SEQ / 128, BATCH), 256>>>(
        p, nullptr, SEQ, x, nullptr, DIM, mix, DIM, SEQ, LLs, LD, LD);

    // hout = act( mix @ Wout[:, :D]^T + q @ Wout[:, D:]^T )   (flattened M)
    if (do_tanh)
        gemm_kernel<true, true, true><<<dim3(DIM / 128, (BATCH * SEQ) / 128, 1), 256>>>(
            mix, q, DIM, Wout, Wout + DIM, 2 * DIM, hout, DIM, DIM, 0, 0, 0);
    else
        gemm_kernel<true, true, false><<<dim3(DIM / 128, (BATCH * SEQ) / 128, 1), 256>>>(
            mix, q, DIM, Wout, Wout + DIM, 2 * DIM, hout, DIM, DIM, 0, 0, 0);
}

extern "C" void kernel_launch(void* const* d_in, const int* in_sizes, int n_in,
                              void* d_out, int out_size)
{
    const float* x     = (const float*)d_in[0];
    const float* Win1  = (const float*)d_in[1];
    const float* Wout1 = (const float*)d_in[2];
    const float* Win2  = (const float*)d_in[3];
    const float* Wout2 = (const float*)d_in[4];
    float* out = (float*)d_out;

    float *q, *p, *mix, *h;
    cudaGetSymbolAddress((void**)&q,   g_q);
    cudaGetSymbolAddress((void**)&p,   g_p);
    cudaGetSymbolAddress((void**)&mix, g_mix);
    cudaGetSymbolAddress((void**)&h,   g_h);

    // Block 1: x -> h (tanh)
    attention_block(x, Win1, Wout1, q, p, mix, h, true);

    // Block 2: h -> p (no tanh). Its out kernel reads only mix & q, so writing
    // the result into p (L==D, identical extent) is safe.
    attention_block(h, Win2, Wout2, q, p, mix, p, false);

    // Mean over L -> [N, D] == [N, D, 1, 1]
    pool_kernel<<<(BATCH * DIM) / 256, 256>>>(p, out);
}

// round 4
// speedup vs baseline: 3.1035x; 3.1012x over previous
#include <cuda_runtime.h>
#include <cuda_bf16.h>
#include <math.h>
#include <stdint.h>

#define BATCH 256
#define SEQ   512
#define DIM   512

static const long NEL = (long)BATCH * SEQ * DIM;  // 67108864

// ---------------------------------------------------------------------------
// Scratch: __device__ globals (allocation-free rule)
// ---------------------------------------------------------------------------
static __device__ __nv_bfloat16 g_xh[67108864], g_xl[67108864];   // X / later h
static __device__ __nv_bfloat16 g_xth[67108864], g_xtl[67108864]; // X^T (block 1)
static __device__ __nv_bfloat16 g_qh[67108864], g_ql[67108864];   // q1 / q2
static __device__ __nv_bfloat16 g_sh[67108864], g_sl[67108864];   // scores / P
static __device__ __nv_bfloat16 g_mh[67108864], g_ml[67108864];   // mix1
static __device__ __nv_bfloat16 g_w1h[262144], g_w1l[262144];
static __device__ __nv_bfloat16 g_wo1h[524288], g_wo1l[524288];
static __device__ __nv_bfloat16 g_w2h[262144], g_w2l[262144];
static __device__ float g_pbar[131072], g_qbar[131072], g_mbar2[131072];

// ---------------------------------------------------------------------------
// PTX helpers (sm_80+ baseline: cp.async / ldmatrix / mma.sync bf16)
// ---------------------------------------------------------------------------
__device__ __forceinline__ void cp_async16(uint32_t s, const void* g) {
    asm volatile("cp.async.cg.shared.global [%0], [%1], 16;"
                 :: "r"(s), "l"(__cvta_generic_to_global(g)) : "memory");
}

__device__ __forceinline__ void ldsm_x4(uint32_t addr, uint32_t& r0, uint32_t& r1,
                                        uint32_t& r2, uint32_t& r3) {
    asm volatile("ldmatrix.sync.aligned.m8n8.x4.shared.b16 {%0,%1,%2,%3}, [%4];"
                 : "=r"(r0), "=r"(r1), "=r"(r2), "=r"(r3) : "r"(addr));
}

__device__ __forceinline__ void ldsm_x2(uint32_t addr, uint32_t& r0, uint32_t& r1) {
    asm volatile("ldmatrix.sync.aligned.m8n8.x2.shared.b16 {%0,%1}, [%2];"
                 : "=r"(r0), "=r"(r1) : "r"(addr));
}

__device__ __forceinline__ void mma16816(float* c, const uint32_t* a, const uint32_t* b) {
    asm volatile("mma.sync.aligned.m16n8k16.row.col.f32.bf16.bf16.f32 "
                 "{%0,%1,%2,%3}, {%4,%5,%6,%7}, {%8,%9}, {%0,%1,%2,%3};"
                 : "+f"(c[0]), "+f"(c[1]), "+f"(c[2]), "+f"(c[3])
                 : "r"(a[0]), "r"(a[1]), "r"(a[2]), "r"(a[3]), "r"(b[0]), "r"(b[1]));
}

// ---------------------------------------------------------------------------
// Split-bf16 HMMA GEMM.
//   C[m,n] = sum_k A[m,k]*B[n,k], A=aH+aL, B=bH+bL, 3-pass (HH+HL+LH) fp32 accum.
//   Block tile 128x128, BK=32, 256 thr (2x4 warps, 64x32 warp tile).
//   DUAL: second (A2,B2) pair over same K (handles [mix,q] concat).
//   Output: tanh (opt) then hi/lo bf16 re-split.
// ---------------------------------------------------------------------------
#define BK      32
#define ROWB    80                    // padded row: 40 bf16 = 80 B (ldmatrix conflict-free)
#define TILE_B  (128 * ROWB)          // 10240 B per tile
#define STAGE_B (4 * TILE_B)          // AH, AL, BH, BL
#define GEMM_DYN_SMEM (2 * STAGE_B)   // 81920 B (double buffered)

__device__ __forceinline__ void load_chunk(uint32_t sbase,
    const __nv_bfloat16* pAH, const __nv_bfloat16* pAL,
    const __nv_bfloat16* pBH, const __nv_bfloat16* pBL,
    long rowA, long colB, int lda, int ldb, int k0, int tid)
{
    const __nv_bfloat16* ptrs[4] = {pAH, pAL, pBH, pBL};
#pragma unroll
    for (int i = 0; i < 8; ++i) {
        int seg = tid + i * 256;          // 0..2047 16B segments
        int t = seg >> 9;                 // tile 0..3
        int r = (seg >> 2) & 127;         // row 0..127
        int c = seg & 3;                  // 16B col chunk 0..3
        long row0 = (t < 2) ? rowA : colB;
        int  ld   = (t < 2) ? lda  : ldb;
        cp_async16(sbase + (uint32_t)(t * TILE_B + r * ROWB + c * 16),
                   ptrs[t] + (row0 + r) * (long)ld + k0 + c * 8);
    }
    asm volatile("cp.async.commit_group;" ::: "memory");
}

template<bool DUAL, bool TANH>
__global__ void __launch_bounds__(256)
gemm_hmma(const __nv_bfloat16* __restrict__ aH, const __nv_bfloat16* __restrict__ aL,
          int lda, long sA,
          const __nv_bfloat16* __restrict__ bH, const __nv_bfloat16* __restrict__ bL,
          int ldb, long sB,
          const __nv_bfloat16* __restrict__ a2H, const __nv_bfloat16* __restrict__ a2L,
          const __nv_bfloat16* __restrict__ b2H, const __nv_bfloat16* __restrict__ b2L,
          __nv_bfloat16* __restrict__ cH, __nv_bfloat16* __restrict__ cL,
          int ldc, long sC, int K)
{
    extern __shared__ char smem_raw[];
    const uint32_t smem = (uint32_t)__cvta_generic_to_shared(smem_raw);

    const int tid  = threadIdx.x;
    const int lane = tid & 31;
    const int wid  = tid >> 5;
    const int wm   = wid & 1;       // 2 m-groups of 64
    const int wn   = wid >> 1;      // 4 n-groups of 32
    const int bz   = blockIdx.z;
    const long rowA = (long)blockIdx.y * 128;
    const long colB = (long)blockIdx.x * 128;

    float acc[4][4][4];
#pragma unroll
    for (int i = 0; i < 4; ++i)
#pragma unroll
        for (int j = 0; j < 4; ++j)
#pragma unroll
            for (int k = 0; k < 4; ++k) acc[i][j][k] = 0.f;

    const int npc    = K / BK;                 // chunks per pair
    const int nchunk = (DUAL ? 2 : 1) * npc;

    const __nv_bfloat16* AH0 = aH + bz * sA;
    const __nv_bfloat16* AL0 = aL + bz * sA;
    const __nv_bfloat16* BH0 = bH + bz * sB;
    const __nv_bfloat16* BL0 = bL + bz * sB;
    const __nv_bfloat16* AH1 = DUAL ? a2H + bz * sA : nullptr;
    const __nv_bfloat16* AL1 = DUAL ? a2L + bz * sA : nullptr;
    const __nv_bfloat16* BH1 = DUAL ? b2H + bz * sB : nullptr;
    const __nv_bfloat16* BL1 = DUAL ? b2L + bz * sB : nullptr;

    // prologue: chunk 0 -> stage 0
    load_chunk(smem, AH0, AL0, BH0, BL0, rowA, colB, lda, ldb, 0, tid);

    for (int c = 0; c < nchunk; ++c) {
        const int stage = c & 1;
        if (c + 1 < nchunk) {
            int cn = c + 1;
            int p  = cn / npc;
            int k0 = (cn % npc) * BK;
            if (!DUAL || p == 0)
                load_chunk(smem + (stage ^ 1) * STAGE_B, AH0, AL0, BH0, BL0,
                           rowA, colB, lda, ldb, k0, tid);
            else
                load_chunk(smem + (stage ^ 1) * STAGE_B, AH1, AL1, BH1, BL1,
                           rowA, colB, lda, ldb, k0, tid);
            asm volatile("cp.async.wait_group 1;" ::: "memory");
        } else {
            asm volatile("cp.async.wait_group 0;" ::: "memory");
        }
        __syncthreads();

        const uint32_t sb = smem + stage * STAGE_B;
        const uint32_t aBase[3] = {sb, sb, sb + TILE_B};                      // AH,AH,AL
        const uint32_t bBase[3] = {sb + 2 * TILE_B, sb + 3 * TILE_B,          // BH,BL,BH
                                   sb + 2 * TILE_B};

#pragma unroll
        for (int p = 0; p < 3; ++p) {
#pragma unroll
            for (int ks = 0; ks < 2; ++ks) {
                uint32_t af[4][4], bf[4][2];
#pragma unroll
                for (int mf = 0; mf < 4; ++mf) {
                    uint32_t addr = aBase[p]
                        + (uint32_t)((wm * 64 + mf * 16 + (lane & 15)) * ROWB
                                     + ks * 32 + (lane >> 4) * 16);
                    ldsm_x4(addr, af[mf][0], af[mf][1], af[mf][2], af[mf][3]);
                }
#pragma unroll
                for (int nf = 0; nf < 4; ++nf) {
                    uint32_t addr = bBase[p]
                        + (uint32_t)((wn * 32 + nf * 8 + (lane & 7)) * ROWB
                                     + ks * 32 + ((lane >> 3) & 1) * 16);
                    ldsm_x2(addr, bf[nf][0], bf[nf][1]);
                }
#pragma unroll
                for (int mf = 0; mf < 4; ++mf)
#pragma unroll
                    for (int nf = 0; nf < 4; ++nf)
                        mma16816(acc[mf][nf], af[mf], bf[nf]);
            }
        }
        __syncthreads();
    }

    // Epilogue: c0,c1 -> (row=t/4, col=(t%4)*2..+1); c2,c3 -> row+8.
    __nv_bfloat16* CH = cH + (long)bz * sC;
    __nv_bfloat16* CL = cL + (long)bz * sC;
    const int rq = lane >> 2, cq = (lane & 3) * 2;

#pragma unroll
    for (int mf = 0; mf < 4; ++mf) {
#pragma unroll
        for (int nf = 0; nf < 4; ++nf) {
            long col = colB + wn * 32 + nf * 8 + cq;
#pragma unroll
            for (int half = 0; half < 2; ++half) {
                long row = rowA + wm * 64 + mf * 16 + rq + half * 8;
                float v0 = acc[mf][nf][half * 2 + 0];
                float v1 = acc[mf][nf][half * 2 + 1];
                if (TANH) { v0 = tanhf(v0); v1 = tanhf(v1); }
                __nv_bfloat16 h0 = __float2bfloat16_rn(v0);
                __nv_bfloat16 h1 = __float2bfloat16_rn(v1);
                __nv_bfloat16 l0 = __float2bfloat16_rn(v0 - __bfloat162float(h0));
                __nv_bfloat16 l1 = __float2bfloat16_rn(v1 - __bfloat162float(h1));
                __nv_bfloat162 hp; hp.x = h0; hp.y = h1;
                __nv_bfloat162 lp; lp.x = l0; lp.y = l1;
                *(__nv_bfloat162*)(CH + row * (long)ldc + col) = hp;
                *(__nv_bfloat162*)(CL + row * (long)ldc + col) = lp;
            }
        }
    }
}

// ---------------------------------------------------------------------------
// fp32 -> (hi, lo) bf16 split, 4 elems/thread
// ---------------------------------------------------------------------------
__global__ void __launch_bounds__(256)
split_kernel(const float4* __restrict__ x, uint2* __restrict__ hi, uint2* __restrict__ lo)
{
    long i = (long)blockIdx.x * blockDim.x + threadIdx.x;
    float4 v = x[i];
    float f[4] = {v.x, v.y, v.z, v.w};
    __nv_bfloat16 h[4], l[4];
#pragma unroll
    for (int j = 0; j < 4; ++j) {
        h[j] = __float2bfloat16_rn(f[j]);
        l[j] = __float2bfloat16_rn(f[j] - __bfloat162float(h[j]));
    }
    __nv_bfloat162 h01, h23, l01, l23;
    h01.x = h[0]; h01.y = h[1]; h23.x = h[2]; h23.y = h[3];
    l01.x = l[0]; l01.y = l[1]; l23.x = l[2]; l23.y = l[3];
    uint2 uh, ul;
    uh.x = *(uint32_t*)&h01; uh.y = *(uint32_t*)&h23;
    ul.x = *(uint32_t*)&l01; ul.y = *(uint32_t*)&l23;
    hi[i] = uh; lo[i] = ul;
}

// ---------------------------------------------------------------------------
// Per-batch 512x512 bf16 transpose
// ---------------------------------------------------------------------------
__global__ void __launch_bounds__(256)
transpose_bf16(const __nv_bfloat16* __restrict__ in, __nv_bfloat16* __restrict__ out)
{
    __shared__ __nv_bfloat16 tile[32][33];
    const long base = (long)blockIdx.z * 262144;
    int x = blockIdx.x * 32 + threadIdx.x;
    int y0 = blockIdx.y * 32;
#pragma unroll
    for (int j = 0; j < 32; j += 8)
        tile[threadIdx.y + j][threadIdx.x] = in[base + (long)(y0 + threadIdx.y + j) * 512 + x];
    __syncthreads();
    int xo = blockIdx.y * 32 + threadIdx.x;
    int yo0 = blockIdx.x * 32;
#pragma unroll
    for (int j = 0; j < 32; j += 8)
        out[base + (long)(yo0 + threadIdx.y + j) * 512 + xo] = tile[threadIdx.x][threadIdx.y + j];
}

// ---------------------------------------------------------------------------
// Row softmax over 512 (hi/lo in, hi/lo out, in place). 128 thr/row.
// ---------------------------------------------------------------------------
__global__ void __launch_bounds__(128)
softmax512_kernel(__nv_bfloat16* __restrict__ SH, __nv_bfloat16* __restrict__ SL)
{
    __shared__ float redm[4], reds[4];
    const long row = blockIdx.x;
    const int t = threadIdx.x;
    uint2* ph = (uint2*)(SH + row * 512);
    uint2* pl = (uint2*)(SL + row * 512);

    uint2 uh = ph[t], ul = pl[t];
    __nv_bfloat162 h01 = *(__nv_bfloat162*)&uh.x, h23 = *(__nv_bfloat162*)&uh.y;
    __nv_bfloat162 l01 = *(__nv_bfloat162*)&ul.x, l23 = *(__nv_bfloat162*)&ul.y;
    float2 fh01 = __bfloat1622float2(h01), fh23 = __bfloat1622float2(h23);
    float2 fl01 = __bfloat1622float2(l01), fl23 = __bfloat1622float2(l23);
    float v[4] = {fh01.x + fl01.x, fh01.y + fl01.y, fh23.x + fl23.x, fh23.y + fl23.y};

    float m = fmaxf(fmaxf(v[0], v[1]), fmaxf(v[2], v[3]));
#pragma unroll
    for (int o = 16; o; o >>= 1) m = fmaxf(m, __shfl_xor_sync(0xffffffffu, m, o));
    if ((t & 31) == 0) redm[t >> 5] = m;
    __syncthreads();
    m = fmaxf(fmaxf(redm[0], redm[1]), fmaxf(redm[2], redm[3]));

    float s = 0.f;
#pragma unroll
    for (int j = 0; j < 4; ++j) { v[j] = __expf(v[j] - m); s += v[j]; }
#pragma unroll
    for (int o = 16; o; o >>= 1) s += __shfl_xor_sync(0xffffffffu, s, o);
    if ((t & 31) == 0) reds[t >> 5] = s;
    __syncthreads();
    s = reds[0] + reds[1] + reds[2] + reds[3];
    float r = 1.0f / s;

    __nv_bfloat16 h[4], l[4];
#pragma unroll
    for (int j = 0; j < 4; ++j) {
        float w = v[j] * r;
        h[j] = __float2bfloat16_rn(w);
        l[j] = __float2bfloat16_rn(w - __bfloat162float(h[j]));
    }
    __nv_bfloat162 oh01, oh23, ol01, ol23;
    oh01.x = h[0]; oh01.y = h[1]; oh23.x = h[2]; oh23.y = h[3];
    ol01.x = l[0]; ol01.y = l[1]; ol23.x = l[2]; ol23.y = l[3];
    uh.x = *(uint32_t*)&oh01; uh.y = *(uint32_t*)&oh23;
    ul.x = *(uint32_t*)&ol01; ul.y = *(uint32_t*)&ol23;
    ph[t] = uh; pl[t] = ul;
}

// ---------------------------------------------------------------------------
// out[b,j] = (1/512) * sum_i (hi+lo)[b,i,j]
// ---------------------------------------------------------------------------
__global__ void __launch_bounds__(512)
meanrows_kernel(const __nv_bfloat16* __restrict__ hi, const __nv_bfloat16* __restrict__ lo,
                float* __restrict__ out)
{
    const long base = (long)blockIdx.x * 262144 + threadIdx.x;
    float s = 0.f;
#pragma unroll 4
    for (int i = 0; i < 512; ++i) {
        long off = base + (long)i * 512;
        s += __bfloat162float(hi[off]) + __bfloat162float(lo[off]);
    }
    out[blockIdx.x * 512 + threadIdx.x] = s * (1.0f / 512.0f);
}

// ---------------------------------------------------------------------------
// mixbar[b,d] = sum_m pbar[b,m] * (hi+lo)(h[b,m,d])
// ---------------------------------------------------------------------------
__global__ void __launch_bounds__(512)
mixbar_kernel(const float* __restrict__ pbar,
              const __nv_bfloat16* __restrict__ hh, const __nv_bfloat16* __restrict__ hl,
              float* __restrict__ mbar)
{
    __shared__ float pb[512];
    const int b = blockIdx.x, d = threadIdx.x;
    pb[d] = pbar[b * 512 + d];
    __syncthreads();
    const long base = (long)b * 262144 + d;
    float s = 0.f;
#pragma unroll 4
    for (int m = 0; m < 512; ++m) {
        long off = base + (long)m * 512;
        s += pb[m] * (__bfloat162float(hh[off]) + __bfloat162float(hl[off]));
    }
    mbar[b * 512 + d] = s;
}

// ---------------------------------------------------------------------------
// out[b,d] = sum_c mixbar[b,c]*W[d,c] + sum_c qbar[b,c]*W[d,512+c]   (W: [512,1024])
// ---------------------------------------------------------------------------
__global__ void __launch_bounds__(512)
final_kernel(const float* __restrict__ mixbar, const float* __restrict__ qbar,
             const float* __restrict__ W, float* __restrict__ out)
{
    __shared__ float mb[512], qb[512];
    const int b = blockIdx.x, d = threadIdx.x;
    mb[d] = mixbar[b * 512 + d];
    qb[d] = qbar[b * 512 + d];
    __syncthreads();
    const float4* w4 = (const float4*)(W + (long)d * 1024);
    float s = 0.f;
#pragma unroll 4
    for (int c4 = 0; c4 < 128; ++c4) {
        float4 w = w4[c4];
        int c = c4 * 4;
        s += mb[c] * w.x + mb[c + 1] * w.y + mb[c + 2] * w.z + mb[c + 3] * w.w;
    }
#pragma unroll 4
    for (int c4 = 128; c4 < 256; ++c4) {
        float4 w = w4[c4];
        int c = c4 * 4 - 512;
        s += qb[c] * w.x + qb[c + 1] * w.y + qb[c + 2] * w.z + qb[c + 3] * w.w;
    }
    out[b * 512 + d] = s;
}

// ---------------------------------------------------------------------------

extern "C" void kernel_launch(void* const* d_in, const int* in_sizes, int n_in,
                              void* d_out, int out_size)
{
    const float* x     = (const float*)d_in[0];
    const float* Win1  = (const float*)d_in[1];
    const float* Wout1 = (const float*)d_in[2];
    const float* Win2  = (const float*)d_in[3];
    const float* Wout2 = (const float*)d_in[4];
    float* out = (float*)d_out;

    __nv_bfloat16 *xh, *xl, *xth, *xtl, *qh, *ql, *sh, *sl, *mh, *ml;
    __nv_bfloat16 *w1h, *w1l, *wo1h, *wo1l, *w2h, *w2l;
    float *pbar, *qbar, *mbar2;
    cudaGetSymbolAddress((void**)&xh,  g_xh);   cudaGetSymbolAddress((void**)&xl,  g_xl);
    cudaGetSymbolAddress((void**)&xth, g_xth);  cudaGetSymbolAddress((void**)&xtl, g_xtl);
    cudaGetSymbolAddress((void**)&qh,  g_qh);   cudaGetSymbolAddress((void**)&ql,  g_ql);
    cudaGetSymbolAddress((void**)&sh,  g_sh);   cudaGetSymbolAddress((void**)&sl,  g_sl);
    cudaGetSymbolAddress((void**)&mh,  g_mh);   cudaGetSymbolAddress((void**)&ml,  g_ml);
    cudaGetSymbolAddress((void**)&w1h, g_w1h);  cudaGetSymbolAddress((void**)&w1l, g_w1l);
    cudaGetSymbolAddress((void**)&wo1h,g_wo1h); cudaGetSymbolAddress((void**)&wo1l,g_wo1l);
    cudaGetSymbolAddress((void**)&w2h, g_w2h);  cudaGetSymbolAddress((void**)&w2l, g_w2l);
    cudaGetSymbolAddress((void**)&pbar, g_pbar);
    cudaGetSymbolAddress((void**)&qbar, g_qbar);
    cudaGetSymbolAddress((void**)&mbar2, g_mbar2);

    cudaFuncSetAttribute(gemm_hmma<false, false>,
                         cudaFuncAttributeMaxDynamicSharedMemorySize, GEMM_DYN_SMEM);
    cudaFuncSetAttribute(gemm_hmma<true, true>,
                         cudaFuncAttributeMaxDynamicSharedMemorySize, GEMM_DYN_SMEM);

    const int  M_FLAT = BATCH * SEQ;     // 131072
    const long LDb = 262144;

    // ---- splits ----
    split_kernel<<<262144 / 4 / 256, 256>>>((const float4*)Win1,  (uint2*)w1h,  (uint2*)w1l);
    split_kernel<<<524288 / 4 / 256, 256>>>((const float4*)Wout1, (uint2*)wo1h, (uint2*)wo1l);
    split_kernel<<<262144 / 4 / 256, 256>>>((const float4*)Win2,  (uint2*)w2h,  (uint2*)w2l);
    split_kernel<<<(int)(NEL / 4 / 256), 256>>>((const float4*)x, (uint2*)xh, (uint2*)xl);
    transpose_bf16<<<dim3(16, 16, 256), dim3(32, 8)>>>(xh, xth);
    transpose_bf16<<<dim3(16, 16, 256), dim3(32, 8)>>>(xl, xtl);

    // ---- block 1 ----
    // q1 = X @ Win1^T
    gemm_hmma<false, false><<<dim3(4, 1024, 1), 256, GEMM_DYN_SMEM>>>(
        xh, xl, 512, 0, w1h, w1l, 512, 0,
        nullptr, nullptr, nullptr, nullptr, qh, ql, 512, 0, 512);
    // S1[b] = q1[b] @ X[b]^T
    gemm_hmma<false, false><<<dim3(4, 4, 256), 256, GEMM_DYN_SMEM>>>(
        qh, ql, 512, LDb, xh, xl, 512, LDb,
        nullptr, nullptr, nullptr, nullptr, sh, sl, 512, LDb, 512);
    softmax512_kernel<<<M_FLAT, 128>>>(sh, sl);
    // mix1[b] = P1[b] @ X[b]   (B = X^T, K-major over m)
    gemm_hmma<false, false><<<dim3(4, 4, 256), 256, GEMM_DYN_SMEM>>>(
        sh, sl, 512, LDb, xth, xtl, 512, LDb,
        nullptr, nullptr, nullptr, nullptr, mh, ml, 512, LDb, 512);
    // h = tanh(mix1 @ Wout1[:, :512]^T + q1 @ Wout1[:, 512:]^T) -> overwrite X slots
    gemm_hmma<true, true><<<dim3(4, 1024, 1), 256, GEMM_DYN_SMEM>>>(
        mh, ml, 512, 0, wo1h, wo1l, 1024, 0,
        qh, ql, wo1h + 512, wo1l + 512, xh, xl, 512, 0, 512);

    // ---- block 2 (pooling collapsed: no mix2 / out-proj GEMMs) ----
    // q2 = h @ Win2^T
    gemm_hmma<false, false><<<dim3(4, 1024, 1), 256, GEMM_DYN_SMEM>>>(
        xh, xl, 512, 0, w2h, w2l, 512, 0,
        nullptr, nullptr, nullptr, nullptr, qh, ql, 512, 0, 512);
    // S2[b] = q2[b] @ h[b]^T
    gemm_hmma<false, false><<<dim3(4, 4, 256), 256, GEMM_DYN_SMEM>>>(
        qh, ql, 512, LDb, xh, xl, 512, LDb,
        nullptr, nullptr, nullptr, nullptr, sh, sl, 512, LDb, 512);
    softmax512_kernel<<<M_FLAT, 128>>>(sh, sl);

    meanrows_kernel<<<BATCH, 512>>>(sh, sl, pbar);   // pbar[b,m] = mean_l P2
    meanrows_kernel<<<BATCH, 512>>>(qh, ql, qbar);   // qbar[b,d] = mean_l q2
    mixbar_kernel<<<BATCH, 512>>>(pbar, xh, xl, mbar2);
    final_kernel<<<BATCH, 512>>>(mbar2, qbar, Wout2, out);
}

// round 5
// speedup vs baseline: 3.4489x; 1.1113x over previous
#include <cuda_runtime.h>
#include <cuda_bf16.h>
#include <math.h>
#include <stdint.h>

#define BATCH 256
#define SEQ   512
#define DIM   512

static const long NEL = (long)BATCH * SEQ * DIM;  // 67108864

// ---------------------------------------------------------------------------
// Scratch: __device__ globals (allocation-free rule)
// ---------------------------------------------------------------------------
static __device__ __nv_bfloat16 g_xh[67108864], g_xl[67108864];   // X / later h
static __device__ __nv_bfloat16 g_xth[67108864], g_xtl[67108864]; // X^T (block 1)
static __device__ __nv_bfloat16 g_qh[67108864], g_ql[67108864];   // q1 / q2
static __device__ __nv_bfloat16 g_sh[67108864], g_sl[67108864];   // P hi/lo
static __device__ __nv_bfloat16 g_mh[67108864], g_ml[67108864];   // mix1
static __device__ float g_sf[67108864];                           // scores fp32
static __device__ __nv_bfloat16 g_w1h[262144], g_w1l[262144];
static __device__ __nv_bfloat16 g_wo1h[524288], g_wo1l[524288];
static __device__ __nv_bfloat16 g_w2h[262144], g_w2l[262144];
static __device__ float g_pbar[131072], g_qbar[131072], g_mbar2[131072];

// ---------------------------------------------------------------------------
// PTX helpers (sm_80+ baseline: cp.async / ldmatrix / mma.sync bf16)
// ---------------------------------------------------------------------------
__device__ __forceinline__ void cp_async16(uint32_t s, const void* g) {
    asm volatile("cp.async.cg.shared.global [%0], [%1], 16;"
                 :: "r"(s), "l"(__cvta_generic_to_global(g)) : "memory");
}

__device__ __forceinline__ void ldsm_x4(uint32_t addr, uint32_t& r0, uint32_t& r1,
                                        uint32_t& r2, uint32_t& r3) {
    asm volatile("ldmatrix.sync.aligned.m8n8.x4.shared.b16 {%0,%1,%2,%3}, [%4];"
                 : "=r"(r0), "=r"(r1), "=r"(r2), "=r"(r3) : "r"(addr));
}

__device__ __forceinline__ void ldsm_x2(uint32_t addr, uint32_t& r0, uint32_t& r1) {
    asm volatile("ldmatrix.sync.aligned.m8n8.x2.shared.b16 {%0,%1}, [%2];"
                 : "=r"(r0), "=r"(r1) : "r"(addr));
}

__device__ __forceinline__ void mma16816(float* c, const uint32_t* a, const uint32_t* b) {
    asm volatile("mma.sync.aligned.m16n8k16.row.col.f32.bf16.bf16.f32 "
                 "{%0,%1,%2,%3}, {%4,%5,%6,%7}, {%8,%9}, {%0,%1,%2,%3};"
                 : "+f"(c[0]), "+f"(c[1]), "+f"(c[2]), "+f"(c[3])
                 : "r"(a[0]), "r"(a[1]), "r"(a[2]), "r"(a[3]), "r"(b[0]), "r"(b[1]));
}

// ---------------------------------------------------------------------------
// Split-bf16 HMMA GEMM.
//   C[m,n] = sum_k A[m,k]*B[n,k], A=aH+aL, B=bH+bL; AH*(BH+BL)+AL*BH fp32 accum.
//   Block tile 128x128, BK=32, 256 thr (2x4 warps, 64x32 warp tile), 2-stage.
//   DUAL: second (A2,B2) pair over same K. OUTF32: fp32 C. TANH: fused tanh.
// ---------------------------------------------------------------------------
#define BK      32
#define ROWB    80                    // padded row: 40 bf16 (ldmatrix conflict-free)
#define TILE_B  (128 * ROWB)          // 10240 B per tile
#define STAGE_B (4 * TILE_B)          // AH, AL, BH, BL
#define GEMM_DYN_SMEM (2 * STAGE_B)   // 81920 B (double buffered)

__device__ __forceinline__ void load_chunk(uint32_t sbase,
    const __nv_bfloat16* pAH, const __nv_bfloat16* pAL,
    const __nv_bfloat16* pBH, const __nv_bfloat16* pBL,
    long rowA, long colB, int lda, int ldb, int k0, int tid)
{
    const __nv_bfloat16* ptrs[4] = {pAH, pAL, pBH, pBL};
#pragma unroll
    for (int i = 0; i < 8; ++i) {
        int seg = tid + i * 256;          // 0..2047 16B segments
        int t = seg >> 9;                 // tile 0..3
        int r = (seg >> 2) & 127;         // row 0..127
        int c = seg & 3;                  // 16B col chunk 0..3
        long row0 = (t < 2) ? rowA : colB;
        int  ld   = (t < 2) ? lda  : ldb;
        cp_async16(sbase + (uint32_t)(t * TILE_B + r * ROWB + c * 16),
                   ptrs[t] + (row0 + r) * (long)ld + k0 + c * 8);
    }
    asm volatile("cp.async.commit_group;" ::: "memory");
}

template<bool DUAL, bool TANH, bool OUTF32>
__global__ void __launch_bounds__(256, 2)
gemm_hmma(const __nv_bfloat16* __restrict__ aH, const __nv_bfloat16* __restrict__ aL,
          int lda, long sA,
          const __nv_bfloat16* __restrict__ bH, const __nv_bfloat16* __restrict__ bL,
          int ldb, long sB,
          const __nv_bfloat16* __restrict__ a2H, const __nv_bfloat16* __restrict__ a2L,
          const __nv_bfloat16* __restrict__ b2H, const __nv_bfloat16* __restrict__ b2L,
          __nv_bfloat16* __restrict__ cH, __nv_bfloat16* __restrict__ cL,
          float* __restrict__ cF,
          int ldc, long sC, int K)
{
    extern __shared__ char smem_raw[];
    const uint32_t smem = (uint32_t)__cvta_generic_to_shared(smem_raw);

    const int tid  = threadIdx.x;
    const int lane = tid & 31;
    const int wid  = tid >> 5;
    const int wm   = wid & 1;       // 2 m-groups of 64
    const int wn   = wid >> 1;      // 4 n-groups of 32
    const int bz   = blockIdx.z;
    const long rowA = (long)blockIdx.y * 128;
    const long colB = (long)blockIdx.x * 128;

    float acc[4][4][4];
#pragma unroll
    for (int i = 0; i < 4; ++i)
#pragma unroll
        for (int j = 0; j < 4; ++j)
#pragma unroll
            for (int k = 0; k < 4; ++k) acc[i][j][k] = 0.f;

    const int npc    = K / BK;                 // chunks per pair
    const int nchunk = (DUAL ? 2 : 1) * npc;

    const __nv_bfloat16* AH0 = aH + bz * sA;
    const __nv_bfloat16* AL0 = aL + bz * sA;
    const __nv_bfloat16* BH0 = bH + bz * sB;
    const __nv_bfloat16* BL0 = bL + bz * sB;
    const __nv_bfloat16* AH1 = DUAL ? a2H + bz * sA : nullptr;
    const __nv_bfloat16* AL1 = DUAL ? a2L + bz * sA : nullptr;
    const __nv_bfloat16* BH1 = DUAL ? b2H + bz * sB : nullptr;
    const __nv_bfloat16* BL1 = DUAL ? b2L + bz * sB : nullptr;

    // prologue: chunk 0 -> stage 0
    load_chunk(smem, AH0, AL0, BH0, BL0, rowA, colB, lda, ldb, 0, tid);

    for (int c = 0; c < nchunk; ++c) {
        const int stage = c & 1;
        if (c + 1 < nchunk) {
            int cn = c + 1;
            int p  = cn / npc;
            int k0 = (cn % npc) * BK;
            if (!DUAL || p == 0)
                load_chunk(smem + (stage ^ 1) * STAGE_B, AH0, AL0, BH0, BL0,
                           rowA, colB, lda, ldb, k0, tid);
            else
                load_chunk(smem + (stage ^ 1) * STAGE_B, AH1, AL1, BH1, BL1,
                           rowA, colB, lda, ldb, k0, tid);
            asm volatile("cp.async.wait_group 1;" ::: "memory");
        } else {
            asm volatile("cp.async.wait_group 0;" ::: "memory");
        }
        __syncthreads();

        const uint32_t sb  = smem + stage * STAGE_B;
        const uint32_t sAH = sb,              sAL = sb + TILE_B;
        const uint32_t sBH = sb + 2 * TILE_B, sBL = sb + 3 * TILE_B;

#pragma unroll
        for (int ks = 0; ks < 2; ++ks) {
            uint32_t bhf[4][2], blf[4][2];
#pragma unroll
            for (int nf = 0; nf < 4; ++nf) {
                uint32_t boff = (uint32_t)((wn * 32 + nf * 8 + (lane & 7)) * ROWB
                                           + ks * 32 + ((lane >> 3) & 1) * 16);
                ldsm_x2(sBH + boff, bhf[nf][0], bhf[nf][1]);
                ldsm_x2(sBL + boff, blf[nf][0], blf[nf][1]);
            }
#pragma unroll
            for (int mf = 0; mf < 4; ++mf) {
                uint32_t aoff = (uint32_t)((wm * 64 + mf * 16 + (lane & 15)) * ROWB
                                           + ks * 32 + (lane >> 4) * 16);
                uint32_t ahf[4], alf[4];
                ldsm_x4(sAH + aoff, ahf[0], ahf[1], ahf[2], ahf[3]);
                ldsm_x4(sAL + aoff, alf[0], alf[1], alf[2], alf[3]);
#pragma unroll
                for (int nf = 0; nf < 4; ++nf) {
                    mma16816(acc[mf][nf], ahf, bhf[nf]);  // hi*hi
                    mma16816(acc[mf][nf], ahf, blf[nf]);  // hi*lo
                    mma16816(acc[mf][nf], alf, bhf[nf]);  // lo*hi
                }
            }
        }
        __syncthreads();
    }

    // Epilogue: c0,c1 -> (row=rq, col=cq..cq+1); c2,c3 -> row+8.
    const int rq = lane >> 2, cq = (lane & 3) * 2;

#pragma unroll
    for (int mf = 0; mf < 4; ++mf) {
#pragma unroll
        for (int nf = 0; nf < 4; ++nf) {
            long col = colB + wn * 32 + nf * 8 + cq;
#pragma unroll
            for (int half = 0; half < 2; ++half) {
                long row = rowA + wm * 64 + mf * 16 + rq + half * 8;
                float v0 = acc[mf][nf][half * 2 + 0];
                float v1 = acc[mf][nf][half * 2 + 1];
                if (OUTF32) {
                    float* CF = cF + (long)bz * sC;
                    *(float2*)(CF + row * (long)ldc + col) = make_float2(v0, v1);
                } else {
                    if (TANH) { v0 = tanhf(v0); v1 = tanhf(v1); }
                    __nv_bfloat16 h0 = __float2bfloat16_rn(v0);
                    __nv_bfloat16 h1 = __float2bfloat16_rn(v1);
                    __nv_bfloat16 l0 = __float2bfloat16_rn(v0 - __bfloat162float(h0));
                    __nv_bfloat16 l1 = __float2bfloat16_rn(v1 - __bfloat162float(h1));
                    __nv_bfloat162 hp; hp.x = h0; hp.y = h1;
                    __nv_bfloat162 lp; lp.x = l0; lp.y = l1;
                    __nv_bfloat16* CH = cH + (long)bz * sC;
                    __nv_bfloat16* CL = cL + (long)bz * sC;
                    *(__nv_bfloat162*)(CH + row * (long)ldc + col) = hp;
                    *(__nv_bfloat162*)(CL + row * (long)ldc + col) = lp;
                }
            }
        }
    }
}

// ---------------------------------------------------------------------------
// fp32 -> (hi, lo) bf16 split, 4 elems/thread
// ---------------------------------------------------------------------------
__device__ __forceinline__ void split4(float4 v, uint2& uh, uint2& ul)
{
    float f[4] = {v.x, v.y, v.z, v.w};
    __nv_bfloat16 h[4], l[4];
#pragma unroll
    for (int j = 0; j < 4; ++j) {
        h[j] = __float2bfloat16_rn(f[j]);
        l[j] = __float2bfloat16_rn(f[j] - __bfloat162float(h[j]));
    }
    __nv_bfloat162 h01, h23, l01, l23;
    h01.x = h[0]; h01.y = h[1]; h23.x = h[2]; h23.y = h[3];
    l01.x = l[0]; l01.y = l[1]; l23.x = l[2]; l23.y = l[3];
    uh.x = *(uint32_t*)&h01; uh.y = *(uint32_t*)&h23;
    ul.x = *(uint32_t*)&l01; ul.y = *(uint32_t*)&l23;
}

__global__ void __launch_bounds__(256)
split_kernel(const float4* __restrict__ x, uint2* __restrict__ hi, uint2* __restrict__ lo)
{
    long i = (long)blockIdx.x * blockDim.x + threadIdx.x;
    uint2 uh, ul;
    split4(x[i], uh, ul);
    hi[i] = uh; lo[i] = ul;
}

// Fused weight split: W1 (65536 f4) | Wout1 (131072 f4) | W2 (65536 f4)
__global__ void __launch_bounds__(256)
wsplit_kernel(const float4* __restrict__ w1, const float4* __restrict__ wo1,
              const float4* __restrict__ w2,
              uint2* __restrict__ w1h, uint2* __restrict__ w1l,
              uint2* __restrict__ wo1h, uint2* __restrict__ wo1l,
              uint2* __restrict__ w2h, uint2* __restrict__ w2l)
{
    long i = (long)blockIdx.x * blockDim.x + threadIdx.x;
    const float4* src; uint2 *dh, *dl; long j;
    if (i < 65536)       { src = w1;  dh = w1h;  dl = w1l;  j = i; }
    else if (i < 196608) { src = wo1; dh = wo1h; dl = wo1l; j = i - 65536; }
    else                 { src = w2;  dh = w2h;  dl = w2l;  j = i - 196608; }
    uint2 uh, ul;
    split4(src[j], uh, ul);
    dh[j] = uh; dl[j] = ul;
}

// ---------------------------------------------------------------------------
// Per-batch 512x512 bf16 transpose
// ---------------------------------------------------------------------------
__global__ void __launch_bounds__(256)
transpose_bf16(const __nv_bfloat16* __restrict__ in, __nv_bfloat16* __restrict__ out)
{
    __shared__ __nv_bfloat16 tile[32][33];
    const long base = (long)blockIdx.z * 262144;
    int x = blockIdx.x * 32 + threadIdx.x;
    int y0 = blockIdx.y * 32;
#pragma unroll
    for (int j = 0; j < 32; j += 8)
        tile[threadIdx.y + j][threadIdx.x] = in[base + (long)(y0 + threadIdx.y + j) * 512 + x];
    __syncthreads();
    int xo = blockIdx.y * 32 + threadIdx.x;
    int yo0 = blockIdx.x * 32;
#pragma unroll
    for (int j = 0; j < 32; j += 8)
        out[base + (long)(yo0 + threadIdx.y + j) * 512 + xo] = tile[threadIdx.x][threadIdx.y + j];
}

// ---------------------------------------------------------------------------
// Row softmax over 512: fp32 in, hi/lo bf16 out. 128 thr/row.
// ---------------------------------------------------------------------------
__global__ void __launch_bounds__(128)
softmax512_f32(const float* __restrict__ S,
               __nv_bfloat16* __restrict__ PH, __nv_bfloat16* __restrict__ PL)
{
    __shared__ float redm[4], reds[4];
    const long row = blockIdx.x;
    const int t = threadIdx.x;

    float4 vv = ((const float4*)(S + row * 512))[t];
    float v[4] = {vv.x, vv.y, vv.z, vv.w};

    float m = fmaxf(fmaxf(v[0], v[1]), fmaxf(v[2], v[3]));
#pragma unroll
    for (int o = 16; o; o >>= 1) m = fmaxf(m, __shfl_xor_sync(0xffffffffu, m, o));
    if ((t & 31) == 0) redm[t >> 5] = m;
    __syncthreads();
    m = fmaxf(fmaxf(redm[0], redm[1]), fmaxf(redm[2], redm[3]));

    float s = 0.f;
#pragma unroll
    for (int j = 0; j < 4; ++j) { v[j] = __expf(v[j] - m); s += v[j]; }
#pragma unroll
    for (int o = 16; o; o >>= 1) s += __shfl_xor_sync(0xffffffffu, s, o);
    if ((t & 31) == 0) reds[t >> 5] = s;
    __syncthreads();
    s = reds[0] + reds[1] + reds[2] + reds[3];
    float r = 1.0f / s;

    float4 w = make_float4(v[0] * r, v[1] * r, v[2] * r, v[3] * r);
    uint2 uh, ul;
    split4(w, uh, ul);
    ((uint2*)(PH + row * 512))[t] = uh;
    ((uint2*)(PL + row * 512))[t] = ul;
}

// ---------------------------------------------------------------------------
// out[b,j] = (1/512) * sum_i (hi+lo)[b,i,j]
// ---------------------------------------------------------------------------
__global__ void __launch_bounds__(512)
meanrows_kernel(const __nv_bfloat16* __restrict__ hi, const __nv_bfloat16* __restrict__ lo,
                float* __restrict__ out)
{
    const long base = (long)blockIdx.x * 262144 + threadIdx.x;
    float s = 0.f;
#pragma unroll 4
    for (int i = 0; i < 512; ++i) {
        long off = base + (long)i * 512;
        s += __bfloat162float(hi[off]) + __bfloat162float(lo[off]);
    }
    out[blockIdx.x * 512 + threadIdx.x] = s * (1.0f / 512.0f);
}

// ---------------------------------------------------------------------------
// mixbar[b,d] = sum_m pbar[b,m] * (hi+lo)(h[b,m,d])
// ---------------------------------------------------------------------------
__global__ void __launch_bounds__(512)
mixbar_kernel(const float* __restrict__ pbar,
              const __nv_bfloat16* __restrict__ hh, const __nv_bfloat16* __restrict__ hl,
              float* __restrict__ mbar)
{
    __shared__ float pb[512];
    const int b = blockIdx.x, d = threadIdx.x;
    pb[d] = pbar[b * 512 + d];
    __syncthreads();
    const long base = (long)b * 262144 + d;
    float s = 0.f;
#pragma unroll 4
    for (int m = 0; m < 512; ++m) {
        long off = base + (long)m * 512;
        s += pb[m] * (__bfloat162float(hh[off]) + __bfloat162float(hl[off]));
    }
    mbar[b * 512 + d] = s;
}

// ---------------------------------------------------------------------------
// out[b,d] = sum_c mixbar[b,c]*W[d,c] + sum_c qbar[b,c]*W[d,512+c]   (W: [512,1024])
// ---------------------------------------------------------------------------
__global__ void __launch_bounds__(512)
final_kernel(const float* __restrict__ mixbar, const float* __restrict__ qbar,
             const float* __restrict__ W, float* __restrict__ out)
{
    __shared__ float mb[512], qb[512];
    const int b = blockIdx.x, d = threadIdx.x;
    mb[d] = mixbar[b * 512 + d];
    qb[d] = qbar[b * 512 + d];
    __syncthreads();
    const float4* w4 = (const float4*)(W + (long)d * 1024);
    float s = 0.f;
#pragma unroll 4
    for (int c4 = 0; c4 < 128; ++c4) {
        float4 w = w4[c4];
        int c = c4 * 4;
        s += mb[c] * w.x + mb[c + 1] * w.y + mb[c + 2] * w.z + mb[c + 3] * w.w;
    }
#pragma unroll 4
    for (int c4 = 128; c4 < 256; ++c4) {
        float4 w = w4[c4];
        int c = c4 * 4 - 512;
        s += qb[c] * w.x + qb[c + 1] * w.y + qb[c + 2] * w.z + qb[c + 3] * w.w;
    }
    out[b * 512 + d] = s;
}

// ---------------------------------------------------------------------------

extern "C" void kernel_launch(void* const* d_in, const int* in_sizes, int n_in,
                              void* d_out, int out_size)
{
    const float* x     = (const float*)d_in[0];
    const float* Win1  = (const float*)d_in[1];
    const float* Wout1 = (const float*)d_in[2];
    const float* Win2  = (const float*)d_in[3];
    const float* Wout2 = (const float*)d_in[4];
    float* out = (float*)d_out;

    __nv_bfloat16 *xh, *xl, *xth, *xtl, *qh, *ql, *sh, *sl, *mh, *ml;
    __nv_bfloat16 *w1h, *w1l, *wo1h, *wo1l, *w2h, *w2l;
    float *sf, *pbar, *qbar, *mbar2;
    cudaGetSymbolAddress((void**)&xh,  g_xh);   cudaGetSymbolAddress((void**)&xl,  g_xl);
    cudaGetSymbolAddress((void**)&xth, g_xth);  cudaGetSymbolAddress((void**)&xtl, g_xtl);
    cudaGetSymbolAddress((void**)&qh,  g_qh);   cudaGetSymbolAddress((void**)&ql,  g_ql);
    cudaGetSymbolAddress((void**)&sh,  g_sh);   cudaGetSymbolAddress((void**)&sl,  g_sl);
    cudaGetSymbolAddress((void**)&mh,  g_mh);   cudaGetSymbolAddress((void**)&ml,  g_ml);
    cudaGetSymbolAddress((void**)&sf,  g_sf);
    cudaGetSymbolAddress((void**)&w1h, g_w1h);  cudaGetSymbolAddress((void**)&w1l, g_w1l);
    cudaGetSymbolAddress((void**)&wo1h,g_wo1h); cudaGetSymbolAddress((void**)&wo1l,g_wo1l);
    cudaGetSymbolAddress((void**)&w2h, g_w2h);  cudaGetSymbolAddress((void**)&w2l, g_w2l);
    cudaGetSymbolAddress((void**)&pbar, g_pbar);
    cudaGetSymbolAddress((void**)&qbar, g_qbar);
    cudaGetSymbolAddress((void**)&mbar2, g_mbar2);

    cudaFuncSetAttribute(gemm_hmma<false, false, false>,
                         cudaFuncAttributeMaxDynamicSharedMemorySize, GEMM_DYN_SMEM);
    cudaFuncSetAttribute(gemm_hmma<false, false, true>,
                         cudaFuncAttributeMaxDynamicSharedMemorySize, GEMM_DYN_SMEM);
    cudaFuncSetAttribute(gemm_hmma<true, true, false>,
                         cudaFuncAttributeMaxDynamicSharedMemorySize, GEMM_DYN_SMEM);

    const int  M_FLAT = BATCH * SEQ;     // 131072
    const long LDb = 262144;

    // ---- splits (2 launches) + transposes (2) => first GEMM at launch idx 4,
    //      S1 GEMM at idx 5 (ncu -s 5 -c 1 captures it) ----
    wsplit_kernel<<<262144 / 256, 256>>>(
        (const float4*)Win1, (const float4*)Wout1, (const float4*)Win2,
        (uint2*)w1h, (uint2*)w1l, (uint2*)wo1h, (uint2*)wo1l, (uint2*)w2h, (uint2*)w2l);
    split_kernel<<<(int)(NEL / 4 / 256), 256>>>((const float4*)x, (uint2*)xh, (uint2*)xl);
    transpose_bf16<<<dim3(16, 16, 256), dim3(32, 8)>>>(xh, xth);
    transpose_bf16<<<dim3(16, 16, 256), dim3(32, 8)>>>(xl, xtl);

    // ---- block 1 ----
    // q1 = X @ Win1^T
    gemm_hmma<false, false, false><<<dim3(4, 1024, 1), 256, GEMM_DYN_SMEM>>>(
        xh, xl, 512, 0, w1h, w1l, 512, 0,
        nullptr, nullptr, nullptr, nullptr, qh, ql, nullptr, 512, 0, 512);
    // S1[b] = q1[b] @ X[b]^T  (fp32 out)
    gemm_hmma<false, false, true><<<dim3(4, 4, 256), 256, GEMM_DYN_SMEM>>>(
        qh, ql, 512, LDb, xh, xl, 512, LDb,
        nullptr, nullptr, nullptr, nullptr, nullptr, nullptr, sf, 512, LDb, 512);
    softmax512_f32<<<M_FLAT, 128>>>(sf, sh, sl);
    // mix1[b] = P1[b] @ X[b]   (B = X^T, K-major over m)
    gemm_hmma<false, false, false><<<dim3(4, 4, 256), 256, GEMM_DYN_SMEM>>>(
        sh, sl, 512, LDb, xth, xtl, 512, LDb,
        nullptr, nullptr, nullptr, nullptr, mh, ml, nullptr, 512, LDb, 512);
    // h = tanh(mix1 @ Wout1[:, :512]^T + q1 @ Wout1[:, 512:]^T) -> overwrite X slots
    gemm_hmma<true, true, false><<<dim3(4, 1024, 1), 256, GEMM_DYN_SMEM>>>(
        mh, ml, 512, 0, wo1h, wo1l, 1024, 0,
        qh, ql, wo1h + 512, wo1l + 512, xh, xl, nullptr, 512, 0, 512);

    // ---- block 2 (pooling collapsed: no mix2 / out-proj GEMMs) ----
    // q2 = h @ Win2^T
    gemm_hmma<false, false, false><<<dim3(4, 1024, 1), 256, GEMM_DYN_SMEM>>>(
        xh, xl, 512, 0, w2h, w2l, 512, 0,
        nullptr, nullptr, nullptr, nullptr, qh, ql, nullptr, 512, 0, 512);
    // S2[b] = q2[b] @ h[b]^T  (fp32 out)
    gemm_hmma<false, false, true><<<dim3(4, 4, 256), 256, GEMM_DYN_SMEM>>>(
        qh, ql, 512, LDb, xh, xl, 512, LDb,
        nullptr, nullptr, nullptr, nullptr, nullptr, nullptr, sf, 512, LDb, 512);
    softmax512_f32<<<M_FLAT, 128>>>(sf, sh, sl);

    meanrows_kernel<<<BATCH, 512>>>(sh, sl, pbar);   // pbar[b,m] = mean_l P2
    meanrows_kernel<<<BATCH, 512>>>(qh, ql, qbar);   // qbar[b,d] = mean_l q2
    mixbar_kernel<<<BATCH, 512>>>(pbar, xh, xl, mbar2);
    final_kernel<<<BATCH, 512>>>(mbar2, qbar, Wout2, out);
}

// round 6
// speedup vs baseline: 3.5450x; 1.0279x over previous
#include <cuda_runtime.h>
#include <cuda_bf16.h>
#include <math.h>
#include <stdint.h>

#define BATCH 256
#define SEQ   512
#define DIM   512

static const long NEL = (long)BATCH * SEQ * DIM;  // 67108864

// ---------------------------------------------------------------------------
// Scratch: __device__ globals (allocation-free rule)
// ---------------------------------------------------------------------------
static __device__ __nv_bfloat16 g_xh[67108864], g_xl[67108864];   // X / later h
static __device__ __nv_bfloat16 g_xth[67108864], g_xtl[67108864]; // X^T (block 1)
static __device__ __nv_bfloat16 g_qh[67108864], g_ql[67108864];   // q1 / q2
static __device__ __nv_bfloat16 g_sh[67108864], g_sl[67108864];   // P hi/lo
static __device__ __nv_bfloat16 g_mh[67108864], g_ml[67108864];   // mix1
static __device__ float g_sf[67108864];                           // scores fp32
static __device__ __nv_bfloat16 g_w1h[262144], g_w1l[262144];
static __device__ __nv_bfloat16 g_wo1h[524288], g_wo1l[524288];
static __device__ __nv_bfloat16 g_w2h[262144], g_w2l[262144];
static __device__ float g_pbar[131072], g_qbar[131072], g_mbar2[131072];

// ---------------------------------------------------------------------------
// PTX helpers (sm_80+ baseline: cp.async / ldmatrix / mma.sync bf16)
// ---------------------------------------------------------------------------
__device__ __forceinline__ void cp_async16(uint32_t s, const void* g) {
    asm volatile("cp.async.cg.shared.global [%0], [%1], 16;"
                 :: "r"(s), "l"(__cvta_generic_to_global(g)) : "memory");
}

__device__ __forceinline__ void ldsm_x4(uint32_t addr, uint32_t& r0, uint32_t& r1,
                                        uint32_t& r2, uint32_t& r3) {
    asm volatile("ldmatrix.sync.aligned.m8n8.x4.shared.b16 {%0,%1,%2,%3}, [%4];"
                 : "=r"(r0), "=r"(r1), "=r"(r2), "=r"(r3) : "r"(addr));
}

__device__ __forceinline__ void mma16816(float* c, const uint32_t* a, const uint32_t* b) {
    asm volatile("mma.sync.aligned.m16n8k16.row.col.f32.bf16.bf16.f32 "
                 "{%0,%1,%2,%3}, {%4,%5,%6,%7}, {%8,%9}, {%0,%1,%2,%3};"
                 : "+f"(c[0]), "+f"(c[1]), "+f"(c[2]), "+f"(c[3])
                 : "r"(a[0]), "r"(a[1]), "r"(a[2]), "r"(a[3]), "r"(b[0]), "r"(b[1]));
}

// ---------------------------------------------------------------------------
// Split-bf16 HMMA GEMM.
//   C[m,n] = sum_k A[m,k]*B[n,k], A=aH+aL, B=bH+bL; AH*BH + AH*BL + AL*BH.
//   Block tile 128x128, BK=32, 256 thr (2x4 warps, 64x32 warp tile),
//   2-stage cp.async pipeline, ONE barrier per chunk.
// ---------------------------------------------------------------------------
#define BK      32
#define ROWB    80                    // padded row: 40 bf16 (ldmatrix conflict-free)
#define TILE_B  (128 * ROWB)          // 10240 B per tile
#define STAGE_B (4 * TILE_B)          // AH, AL, BH, BL
#define GEMM_DYN_SMEM (2 * STAGE_B)   // 81920 B (double buffered)

__device__ __forceinline__ void load_chunk(uint32_t sbase,
    const __nv_bfloat16* pAH, const __nv_bfloat16* pAL,
    const __nv_bfloat16* pBH, const __nv_bfloat16* pBL,
    long rowA, long colB, int lda, int ldb, int k0, int tid)
{
    const __nv_bfloat16* ptrs[4] = {pAH, pAL, pBH, pBL};
#pragma unroll
    for (int i = 0; i < 8; ++i) {
        int seg = tid + i * 256;          // 0..2047 16B segments
        int t = seg >> 9;                 // tile 0..3
        int r = (seg >> 2) & 127;         // row 0..127
        int c = seg & 3;                  // 16B col chunk 0..3
        long row0 = (t < 2) ? rowA : colB;
        int  ld   = (t < 2) ? lda  : ldb;
        cp_async16(sbase + (uint32_t)(t * TILE_B + r * ROWB + c * 16),
                   ptrs[t] + (row0 + r) * (long)ld + k0 + c * 8);
    }
    asm volatile("cp.async.commit_group;" ::: "memory");
}

template<bool DUAL, bool TANH, bool OUTF32>
__global__ void __launch_bounds__(256, 2)
gemm_hmma(const __nv_bfloat16* __restrict__ aH, const __nv_bfloat16* __restrict__ aL,
          int lda, long sA,
          const __nv_bfloat16* __restrict__ bH, const __nv_bfloat16* __restrict__ bL,
          int ldb, long sB,
          const __nv_bfloat16* __restrict__ a2H, const __nv_bfloat16* __restrict__ a2L,
          const __nv_bfloat16* __restrict__ b2H, const __nv_bfloat16* __restrict__ b2L,
          __nv_bfloat16* __restrict__ cH, __nv_bfloat16* __restrict__ cL,
          float* __restrict__ cF,
          int ldc, long sC, int K)
{
    extern __shared__ char smem_raw[];
    const uint32_t smem = (uint32_t)__cvta_generic_to_shared(smem_raw);

    const int tid  = threadIdx.x;
    const int lane = tid & 31;
    const int wid  = tid >> 5;
    const int wm   = wid & 1;       // 2 m-groups of 64
    const int wn   = wid >> 1;      // 4 n-groups of 32
    const int bz   = blockIdx.z;
    const long rowA = (long)blockIdx.y * 128;
    const long colB = (long)blockIdx.x * 128;

    float acc[4][4][4];
#pragma unroll
    for (int i = 0; i < 4; ++i)
#pragma unroll
        for (int j = 0; j < 4; ++j)
#pragma unroll
            for (int k = 0; k < 4; ++k) acc[i][j][k] = 0.f;

    const int npc    = K / BK;                 // chunks per pair
    const int nchunk = (DUAL ? 2 : 1) * npc;

    const __nv_bfloat16* AH0 = aH + bz * sA;
    const __nv_bfloat16* AL0 = aL + bz * sA;
    const __nv_bfloat16* BH0 = bH + bz * sB;
    const __nv_bfloat16* BL0 = bL + bz * sB;
    const __nv_bfloat16* AH1 = DUAL ? a2H + bz * sA : nullptr;
    const __nv_bfloat16* AL1 = DUAL ? a2L + bz * sA : nullptr;
    const __nv_bfloat16* BH1 = DUAL ? b2H + bz * sB : nullptr;
    const __nv_bfloat16* BL1 = DUAL ? b2L + bz * sB : nullptr;

    // precomputed per-thread fragment offsets (within a stage buffer)
    const uint32_t aoffBase = (uint32_t)((wm * 64 + (lane & 15)) * ROWB + (lane >> 4) * 16);
    const uint32_t boffBase = (uint32_t)((wn * 32 + ((lane >> 4) << 3) + (lane & 7)) * ROWB
                                         + ((lane >> 3) & 1) * 16);

    // prologue: chunk 0 -> stage 0
    load_chunk(smem, AH0, AL0, BH0, BL0, rowA, colB, lda, ldb, 0, tid);

    for (int c = 0; c < nchunk; ++c) {
        const int stage = c & 1;
        asm volatile("cp.async.wait_group 0;" ::: "memory");
        __syncthreads();   // buf 'stage' ready; all warps done with buf 'stage^1'

        if (c + 1 < nchunk) {
            int cn = c + 1;
            int p  = cn / npc;
            int k0 = (cn % npc) * BK;
            if (!DUAL || p == 0)
                load_chunk(smem + (stage ^ 1) * STAGE_B, AH0, AL0, BH0, BL0,
                           rowA, colB, lda, ldb, k0, tid);
            else
                load_chunk(smem + (stage ^ 1) * STAGE_B, AH1, AL1, BH1, BL1,
                           rowA, colB, lda, ldb, k0, tid);
        }

        const uint32_t sb  = smem + stage * STAGE_B;
        const uint32_t sAH = sb,              sAL = sb + TILE_B;
        const uint32_t sBH = sb + 2 * TILE_B, sBL = sb + 3 * TILE_B;

#pragma unroll
        for (int ks = 0; ks < 2; ++ks) {
            uint32_t bhf[4][2], blf[4][2];
#pragma unroll
            for (int np = 0; np < 2; ++np) {   // 2 n-frag pairs per x4
                uint32_t boff = boffBase + (uint32_t)(np * 16 * ROWB + ks * 32);
                ldsm_x4(sBH + boff, bhf[2 * np][0], bhf[2 * np][1],
                                    bhf[2 * np + 1][0], bhf[2 * np + 1][1]);
                ldsm_x4(sBL + boff, blf[2 * np][0], blf[2 * np][1],
                                    blf[2 * np + 1][0], blf[2 * np + 1][1]);
            }
#pragma unroll
            for (int mf = 0; mf < 4; ++mf) {
                uint32_t aoff = aoffBase + (uint32_t)(mf * 16 * ROWB + ks * 32);
                uint32_t ahf[4], alf[4];
                ldsm_x4(sAH + aoff, ahf[0], ahf[1], ahf[2], ahf[3]);
                ldsm_x4(sAL + aoff, alf[0], alf[1], alf[2], alf[3]);
#pragma unroll
                for (int nf = 0; nf < 4; ++nf) {
                    mma16816(acc[mf][nf], ahf, bhf[nf]);  // hi*hi
                    mma16816(acc[mf][nf], ahf, blf[nf]);  // hi*lo
                    mma16816(acc[mf][nf], alf, bhf[nf]);  // lo*hi
                }
            }
        }
    }

    // Epilogue: c0,c1 -> (row=rq, col=cq..cq+1); c2,c3 -> row+8.
    const int rq = lane >> 2, cq = (lane & 3) * 2;

#pragma unroll
    for (int mf = 0; mf < 4; ++mf) {
#pragma unroll
        for (int nf = 0; nf < 4; ++nf) {
            long col = colB + wn * 32 + nf * 8 + cq;
#pragma unroll
            for (int half = 0; half < 2; ++half) {
                long row = rowA + wm * 64 + mf * 16 + rq + half * 8;
                float v0 = acc[mf][nf][half * 2 + 0];
                float v1 = acc[mf][nf][half * 2 + 1];
                if (OUTF32) {
                    float* CF = cF + (long)bz * sC;
                    *(float2*)(CF + row * (long)ldc + col) = make_float2(v0, v1);
                } else {
                    if (TANH) { v0 = tanhf(v0); v1 = tanhf(v1); }
                    __nv_bfloat16 h0 = __float2bfloat16_rn(v0);
                    __nv_bfloat16 h1 = __float2bfloat16_rn(v1);
                    __nv_bfloat16 l0 = __float2bfloat16_rn(v0 - __bfloat162float(h0));
                    __nv_bfloat16 l1 = __float2bfloat16_rn(v1 - __bfloat162float(h1));
                    __nv_bfloat162 hp; hp.x = h0; hp.y = h1;
                    __nv_bfloat162 lp; lp.x = l0; lp.y = l1;
                    __nv_bfloat16* CH = cH + (long)bz * sC;
                    __nv_bfloat16* CL = cL + (long)bz * sC;
                    *(__nv_bfloat162*)(CH + row * (long)ldc + col) = hp;
                    *(__nv_bfloat162*)(CL + row * (long)ldc + col) = lp;
                }
            }
        }
    }
}

// ---------------------------------------------------------------------------
// fp32 -> (hi, lo) bf16 split, 4 elems/thread
// ---------------------------------------------------------------------------
__device__ __forceinline__ void split4(float4 v, uint2& uh, uint2& ul)
{
    float f[4] = {v.x, v.y, v.z, v.w};
    __nv_bfloat16 h[4], l[4];
#pragma unroll
    for (int j = 0; j < 4; ++j) {
        h[j] = __float2bfloat16_rn(f[j]);
        l[j] = __float2bfloat16_rn(f[j] - __bfloat162float(h[j]));
    }
    __nv_bfloat162 h01, h23, l01, l23;
    h01.x = h[0]; h01.y = h[1]; h23.x = h[2]; h23.y = h[3];
    l01.x = l[0]; l01.y = l[1]; l23.x = l[2]; l23.y = l[3];
    uh.x = *(uint32_t*)&h01; uh.y = *(uint32_t*)&h23;
    ul.x = *(uint32_t*)&l01; ul.y = *(uint32_t*)&l23;
}

__global__ void __launch_bounds__(256)
split_kernel(const float4* __restrict__ x, uint2* __restrict__ hi, uint2* __restrict__ lo)
{
    long i = (long)blockIdx.x * blockDim.x + threadIdx.x;
    uint2 uh, ul;
    split4(x[i], uh, ul);
    hi[i] = uh; lo[i] = ul;
}

// Fused weight split: W1 (65536 f4) | Wout1 (131072 f4) | W2 (65536 f4)
__global__ void __launch_bounds__(256)
wsplit_kernel(const float4* __restrict__ w1, const float4* __restrict__ wo1,
              const float4* __restrict__ w2,
              uint2* __restrict__ w1h, uint2* __restrict__ w1l,
              uint2* __restrict__ wo1h, uint2* __restrict__ wo1l,
              uint2* __restrict__ w2h, uint2* __restrict__ w2l)
{
    long i = (long)blockIdx.x * blockDim.x + threadIdx.x;
    const float4* src; uint2 *dh, *dl; long j;
    if (i < 65536)       { src = w1;  dh = w1h;  dl = w1l;  j = i; }
    else if (i < 196608) { src = wo1; dh = wo1h; dl = wo1l; j = i - 65536; }
    else                 { src = w2;  dh = w2h;  dl = w2l;  j = i - 196608; }
    uint2 uh, ul;
    split4(src[j], uh, ul);
    dh[j] = uh; dl[j] = ul;
}

// ---------------------------------------------------------------------------
// Per-batch 512x512 bf16 transpose; z in [0,512): z<256 -> hi arrays, else lo.
// ---------------------------------------------------------------------------
__global__ void __launch_bounds__(256)
transpose2_bf16(const __nv_bfloat16* __restrict__ in_h, __nv_bfloat16* __restrict__ out_h,
                const __nv_bfloat16* __restrict__ in_l, __nv_bfloat16* __restrict__ out_l)
{
    __shared__ __nv_bfloat16 tile[32][33];
    const int z = blockIdx.z;
    const bool lo = z >= 256;
    const __nv_bfloat16* in  = lo ? in_l  : in_h;
    __nv_bfloat16*       out = lo ? out_l : out_h;
    const long base = (long)(z & 255) * 262144;
    int x = blockIdx.x * 32 + threadIdx.x;
    int y0 = blockIdx.y * 32;
#pragma unroll
    for (int j = 0; j < 32; j += 8)
        tile[threadIdx.y + j][threadIdx.x] = in[base + (long)(y0 + threadIdx.y + j) * 512 + x];
    __syncthreads();
    int xo = blockIdx.y * 32 + threadIdx.x;
    int yo0 = blockIdx.x * 32;
#pragma unroll
    for (int j = 0; j < 32; j += 8)
        out[base + (long)(yo0 + threadIdx.y + j) * 512 + xo] = tile[threadIdx.x][threadIdx.y + j];
}

// ---------------------------------------------------------------------------
// Row softmax over 512: fp32 in, hi/lo bf16 out. 128 thr/row.
// ---------------------------------------------------------------------------
__global__ void __launch_bounds__(128)
softmax512_f32(const float* __restrict__ S,
               __nv_bfloat16* __restrict__ PH, __nv_bfloat16* __restrict__ PL)
{
    __shared__ float redm[4], reds[4];
    const long row = blockIdx.x;
    const int t = threadIdx.x;

    float4 vv = ((const float4*)(S + row * 512))[t];
    float v[4] = {vv.x, vv.y, vv.z, vv.w};

    float m = fmaxf(fmaxf(v[0], v[1]), fmaxf(v[2], v[3]));
#pragma unroll
    for (int o = 16; o; o >>= 1) m = fmaxf(m, __shfl_xor_sync(0xffffffffu, m, o));
    if ((t & 31) == 0) redm[t >> 5] = m;
    __syncthreads();
    m = fmaxf(fmaxf(redm[0], redm[1]), fmaxf(redm[2], redm[3]));

    float s = 0.f;
#pragma unroll
    for (int j = 0; j < 4; ++j) { v[j] = __expf(v[j] - m); s += v[j]; }
#pragma unroll
    for (int o = 16; o; o >>= 1) s += __shfl_xor_sync(0xffffffffu, s, o);
    if ((t & 31) == 0) reds[t >> 5] = s;
    __syncthreads();
    s = reds[0] + reds[1] + reds[2] + reds[3];
    float r = 1.0f / s;

    float4 w = make_float4(v[0] * r, v[1] * r, v[2] * r, v[3] * r);
    uint2 uh, ul;
    split4(w, uh, ul);
    ((uint2*)(PH + row * 512))[t] = uh;
    ((uint2*)(PL + row * 512))[t] = ul;
}

// ---------------------------------------------------------------------------
// out[b,j] = (1/512) * sum_i (hi+lo)[b,i,j]
// ---------------------------------------------------------------------------
__global__ void __launch_bounds__(512)
meanrows_kernel(const __nv_bfloat16* __restrict__ hi, const __nv_bfloat16* __restrict__ lo,
                float* __restrict__ out)
{
    const long base = (long)blockIdx.x * 262144 + threadIdx.x;
    float s = 0.f;
#pragma unroll 4
    for (int i = 0; i < 512; ++i) {
        long off = base + (long)i * 512;
        s += __bfloat162float(hi[off]) + __bfloat162float(lo[off]);
    }
    out[blockIdx.x * 512 + threadIdx.x] = s * (1.0f / 512.0f);
}

// ---------------------------------------------------------------------------
// mixbar[b,d] = sum_m pbar[b,m] * (hi+lo)(h[b,m,d])
// ---------------------------------------------------------------------------
__global__ void __launch_bounds__(512)
mixbar_kernel(const float* __restrict__ pbar,
              const __nv_bfloat16* __restrict__ hh, const __nv_bfloat16* __restrict__ hl,
              float* __restrict__ mbar)
{
    __shared__ float pb[512];
    const int b = blockIdx.x, d = threadIdx.x;
    pb[d] = pbar[b * 512 + d];
    __syncthreads();
    const long base = (long)b * 262144 + d;
    float s = 0.f;
#pragma unroll 4
    for (int m = 0; m < 512; ++m) {
        long off = base + (long)m * 512;
        s += pb[m] * (__bfloat162float(hh[off]) + __bfloat162float(hl[off]));
    }
    mbar[b * 512 + d] = s;
}

// ---------------------------------------------------------------------------
// out[b,d] = sum_c mixbar[b,c]*W[d,c] + sum_c qbar[b,c]*W[d,512+c]   (W: [512,1024])
// ---------------------------------------------------------------------------
__global__ void __launch_bounds__(512)
final_kernel(const float* __restrict__ mixbar, const float* __restrict__ qbar,
             const float* __restrict__ W, float* __restrict__ out)
{
    __shared__ float mb[512], qb[512];
    const int b = blockIdx.x, d = threadIdx.x;
    mb[d] = mixbar[b * 512 + d];
    qb[d] = qbar[b * 512 + d];
    __syncthreads();
    const float4* w4 = (const float4*)(W + (long)d * 1024);
    float s = 0.f;
#pragma unroll 4
    for (int c4 = 0; c4 < 128; ++c4) {
        float4 w = w4[c4];
        int c = c4 * 4;
        s += mb[c] * w.x + mb[c + 1] * w.y + mb[c + 2] * w.z + mb[c + 3] * w.w;
    }
#pragma unroll 4
    for (int c4 = 128; c4 < 256; ++c4) {
        float4 w = w4[c4];
        int c = c4 * 4 - 512;
        s += qb[c] * w.x + qb[c + 1] * w.y + qb[c + 2] * w.z + qb[c + 3] * w.w;
    }
    out[b * 512 + d] = s;
}

// ---------------------------------------------------------------------------

extern "C" void kernel_launch(void* const* d_in, const int* in_sizes, int n_in,
                              void* d_out, int out_size)
{
    const float* x     = (const float*)d_in[0];
    const float* Win1  = (const float*)d_in[1];
    const float* Wout1 = (const float*)d_in[2];
    const float* Win2  = (const float*)d_in[3];
    const float* Wout2 = (const float*)d_in[4];
    float* out = (float*)d_out;

    __nv_bfloat16 *xh, *xl, *xth, *xtl, *qh, *ql, *sh, *sl, *mh, *ml;
    __nv_bfloat16 *w1h, *w1l, *wo1h, *wo1l, *w2h, *w2l;
    float *sf, *pbar, *qbar, *mbar2;
    cudaGetSymbolAddress((void**)&xh,  g_xh);   cudaGetSymbolAddress((void**)&xl,  g_xl);
    cudaGetSymbolAddress((void**)&xth, g_xth);  cudaGetSymbolAddress((void**)&xtl, g_xtl);
    cudaGetSymbolAddress((void**)&qh,  g_qh);   cudaGetSymbolAddress((void**)&ql,  g_ql);
    cudaGetSymbolAddress((void**)&sh,  g_sh);   cudaGetSymbolAddress((void**)&sl,  g_sl);
    cudaGetSymbolAddress((void**)&mh,  g_mh);   cudaGetSymbolAddress((void**)&ml,  g_ml);
    cudaGetSymbolAddress((void**)&sf,  g_sf);
    cudaGetSymbolAddress((void**)&w1h, g_w1h);  cudaGetSymbolAddress((void**)&w1l, g_w1l);
    cudaGetSymbolAddress((void**)&wo1h,g_wo1h); cudaGetSymbolAddress((void**)&wo1l,g_wo1l);
    cudaGetSymbolAddress((void**)&w2h, g_w2h);  cudaGetSymbolAddress((void**)&w2l, g_w2l);
    cudaGetSymbolAddress((void**)&pbar, g_pbar);
    cudaGetSymbolAddress((void**)&qbar, g_qbar);
    cudaGetSymbolAddress((void**)&mbar2, g_mbar2);

    cudaFuncSetAttribute(gemm_hmma<false, false, false>,
                         cudaFuncAttributeMaxDynamicSharedMemorySize, GEMM_DYN_SMEM);
    cudaFuncSetAttribute(gemm_hmma<false, false, true>,
                         cudaFuncAttributeMaxDynamicSharedMemorySize, GEMM_DYN_SMEM);
    cudaFuncSetAttribute(gemm_hmma<true, true, false>,
                         cudaFuncAttributeMaxDynamicSharedMemorySize, GEMM_DYN_SMEM);

    const int  M_FLAT = BATCH * SEQ;     // 131072
    const long LDb = 262144;

    // ---- splits + fused transpose ----
    wsplit_kernel<<<262144 / 256, 256>>>(
        (const float4*)Win1, (const float4*)Wout1, (const float4*)Win2,
        (uint2*)w1h, (uint2*)w1l, (uint2*)wo1h, (uint2*)wo1l, (uint2*)w2h, (uint2*)w2l);
    split_kernel<<<(int)(NEL / 4 / 256), 256>>>((const float4*)x, (uint2*)xh, (uint2*)xl);
    transpose2_bf16<<<dim3(16, 16, 512), dim3(32, 8)>>>(xh, xth, xl, xtl);

    // ---- block 1 ----
    // q1 = X @ Win1^T
    gemm_hmma<false, false, false><<<dim3(4, 1024, 1), 256, GEMM_DYN_SMEM>>>(
        xh, xl, 512, 0, w1h, w1l, 512, 0,
        nullptr, nullptr, nullptr, nullptr, qh, ql, nullptr, 512, 0, 512);
    // S1[b] = q1[b] @ X[b]^T  (fp32 out)
    gemm_hmma<false, false, true><<<dim3(4, 4, 256), 256, GEMM_DYN_SMEM>>>(
        qh, ql, 512, LDb, xh, xl, 512, LDb,
        nullptr, nullptr, nullptr, nullptr, nullptr, nullptr, sf, 512, LDb, 512);
    softmax512_f32<<<M_FLAT, 128>>>(sf, sh, sl);
    // mix1[b] = P1[b] @ X[b]   (B = X^T, K-major over m)
    gemm_hmma<false, false, false><<<dim3(4, 4, 256), 256, GEMM_DYN_SMEM>>>(
        sh, sl, 512, LDb, xth, xtl, 512, LDb,
        nullptr, nullptr, nullptr, nullptr, mh, ml, nullptr, 512, LDb, 512);
    // h = tanh(mix1 @ Wout1[:, :512]^T + q1 @ Wout1[:, 512:]^T) -> overwrite X slots
    gemm_hmma<true, true, false><<<dim3(4, 1024, 1), 256, GEMM_DYN_SMEM>>>(
        mh, ml, 512, 0, wo1h, wo1l, 1024, 0,
        qh, ql, wo1h + 512, wo1l + 512, xh, xl, nullptr, 512, 0, 512);

    // ---- block 2 (pooling collapsed: no mix2 / out-proj GEMMs) ----
    // q2 = h @ Win2^T
    gemm_hmma<false, false, false><<<dim3(4, 1024, 1), 256, GEMM_DYN_SMEM>>>(
        xh, xl, 512, 0, w2h, w2l, 512, 0,
        nullptr, nullptr, nullptr, nullptr, qh, ql, nullptr, 512, 0, 512);
    // S2[b] = q2[b] @ h[b]^T  (fp32 out)
    gemm_hmma<false, false, true><<<dim3(4, 4, 256), 256, GEMM_DYN_SMEM>>>(
        qh, ql, 512, LDb, xh, xl, 512, LDb,
        nullptr, nullptr, nullptr, nullptr, nullptr, nullptr, sf, 512, LDb, 512);
    softmax512_f32<<<M_FLAT, 128>>>(sf, sh, sl);

    meanrows_kernel<<<BATCH, 512>>>(sh, sl, pbar);   // pbar[b,m] = mean_l P2
    meanrows_kernel<<<BATCH, 512>>>(qh, ql, qbar);   // qbar[b,d] = mean_l q2
    mixbar_kernel<<<BATCH, 512>>>(pbar, xh, xl, mbar2);
    final_kernel<<<BATCH, 512>>>(mbar2, qbar, Wout2, out);
}

// round 7
// speedup vs baseline: 3.8124x; 1.0754x over previous
#include <cuda_runtime.h>
#include <cuda_bf16.h>
#include <math.h>
#include <stdint.h>

#define BATCH 256
#define SEQ   512
#define DIM   512

static const long NEL = (long)BATCH * SEQ * DIM;  // 67108864

// ---------------------------------------------------------------------------
// Scratch: __device__ globals (allocation-free rule)
// ---------------------------------------------------------------------------
static __device__ __nv_bfloat16 g_xh[67108864], g_xl[67108864];   // X / later h
static __device__ __nv_bfloat16 g_xth[67108864], g_xtl[67108864]; // X^T (block 1)
static __device__ __nv_bfloat16 g_qh[67108864], g_ql[67108864];   // q1 / q2
static __device__ __nv_bfloat16 g_sh[67108864], g_sl[67108864];   // P hi/lo
static __device__ __nv_bfloat16 g_mh[67108864], g_ml[67108864];   // mix1
static __device__ float g_sf[67108864];                           // scores fp32
static __device__ __nv_bfloat16 g_w1h[262144], g_w1l[262144];
static __device__ __nv_bfloat16 g_wo1h[524288], g_wo1l[524288];
static __device__ __nv_bfloat16 g_w2h[262144], g_w2l[262144];
static __device__ float g_pbar[131072], g_qbar[131072], g_mbar2[131072];

// ---------------------------------------------------------------------------
// PTX helpers (sm_80+ baseline: cp.async / ldmatrix / mma.sync bf16)
// ---------------------------------------------------------------------------
__device__ __forceinline__ void cp_async16(uint32_t s, const void* g) {
    asm volatile("cp.async.cg.shared.global [%0], [%1], 16;"
                 :: "r"(s), "l"(__cvta_generic_to_global(g)) : "memory");
}

__device__ __forceinline__ void ldsm_x4(uint32_t addr, uint32_t& r0, uint32_t& r1,
                                        uint32_t& r2, uint32_t& r3) {
    asm volatile("ldmatrix.sync.aligned.m8n8.x4.shared.b16 {%0,%1,%2,%3}, [%4];"
                 : "=r"(r0), "=r"(r1), "=r"(r2), "=r"(r3) : "r"(addr));
}

__device__ __forceinline__ void mma16816(float* c, const uint32_t* a, const uint32_t* b) {
    asm volatile("mma.sync.aligned.m16n8k16.row.col.f32.bf16.bf16.f32 "
                 "{%0,%1,%2,%3}, {%4,%5,%6,%7}, {%8,%9}, {%0,%1,%2,%3};"
                 : "+f"(c[0]), "+f"(c[1]), "+f"(c[2]), "+f"(c[3])
                 : "r"(a[0]), "r"(a[1]), "r"(a[2]), "r"(a[3]), "r"(b[0]), "r"(b[1]));
}

// ---------------------------------------------------------------------------
// Split-bf16 HMMA GEMM.
//   C[m,n] = sum_k A[m,k]*B[n,k], A=aH+aL, B=bH+bL; AH*BH + AH*BL + AL*BH.
//   Block tile 128x128, BK=32, 256 thr (2x4 warps, 64x32 warp tile).
//   SMEM: packed rows of 128B = [hi 64B | lo 64B], SW128 XOR swizzle,
//   3-stage cp.async pipeline (wait_group 1), one barrier per chunk.
// ---------------------------------------------------------------------------
#define BK      32
#define TILE_B  (128 * 128)           // 16384 B: one operand (hi+lo packed)
#define STAGE_B (2 * TILE_B)          // A, B
#define NSTAGE  3
#define GEMM_DYN_SMEM (NSTAGE * STAGE_B)   // 98304 B

// byte-offset swizzle within a 128B row: granule g (16B) at row r -> g ^ (r&7)
__device__ __forceinline__ void load_chunk(uint32_t sbase,
    const __nv_bfloat16* pAH, const __nv_bfloat16* pAL,
    const __nv_bfloat16* pBH, const __nv_bfloat16* pBL,
    long rowA, long colB, int lda, int ldb, int k0, int tid)
{
#pragma unroll
    for (int i = 0; i < 8; ++i) {
        int seg = tid + i * 256;            // 0..2047 16B segments
        int t   = seg >> 10;                // 0=A, 1=B
        int r   = (seg >> 3) & 127;         // row 0..127
        int g   = seg & 7;                  // granule 0..7 (0-3 hi, 4-7 lo)
        int c16 = g & 3;
        const __nv_bfloat16* src =
            (t ? ((g & 4) ? pBL : pBH) : ((g & 4) ? pAL : pAH));
        long row0 = t ? colB : rowA;
        int  ld   = t ? ldb  : lda;
        cp_async16(sbase + (uint32_t)(t * TILE_B + r * 128 + ((g ^ (r & 7)) * 16)),
                   src + (row0 + r) * (long)ld + k0 + c16 * 8);
    }
    asm volatile("cp.async.commit_group;" ::: "memory");
}

template<bool DUAL, bool TANH, bool OUTF32>
__global__ void __launch_bounds__(256, 2)
gemm_hmma(const __nv_bfloat16* __restrict__ aH, const __nv_bfloat16* __restrict__ aL,
          int lda, long sA,
          const __nv_bfloat16* __restrict__ bH, const __nv_bfloat16* __restrict__ bL,
          int ldb, long sB,
          const __nv_bfloat16* __restrict__ a2H, const __nv_bfloat16* __restrict__ a2L,
          const __nv_bfloat16* __restrict__ b2H, const __nv_bfloat16* __restrict__ b2L,
          __nv_bfloat16* __restrict__ cH, __nv_bfloat16* __restrict__ cL,
          float* __restrict__ cF,
          int ldc, long sC, int K)
{
    extern __shared__ char smem_raw[];
    const uint32_t smem = (uint32_t)__cvta_generic_to_shared(smem_raw);

    const int tid  = threadIdx.x;
    const int lane = tid & 31;
    const int wid  = tid >> 5;
    const int wm   = wid & 1;       // 2 m-groups of 64
    const int wn   = wid >> 1;      // 4 n-groups of 32
    const int bz   = blockIdx.z;
    const long rowA = (long)blockIdx.y * 128;
    const long colB = (long)blockIdx.x * 128;

    float acc[4][4][4];
#pragma unroll
    for (int i = 0; i < 4; ++i)
#pragma unroll
        for (int j = 0; j < 4; ++j)
#pragma unroll
            for (int k = 0; k < 4; ++k) acc[i][j][k] = 0.f;

    const int npc    = K / BK;                 // chunks per pair
    const int nchunk = (DUAL ? 2 : 1) * npc;

    const __nv_bfloat16* AH0 = aH + bz * sA;
    const __nv_bfloat16* AL0 = aL + bz * sA;
    const __nv_bfloat16* BH0 = bH + bz * sB;
    const __nv_bfloat16* BL0 = bL + bz * sB;
    const __nv_bfloat16* AH1 = DUAL ? a2H + bz * sA : nullptr;
    const __nv_bfloat16* AL1 = DUAL ? a2L + bz * sA : nullptr;
    const __nv_bfloat16* BH1 = DUAL ? b2H + bz * sB : nullptr;
    const __nv_bfloat16* BL1 = DUAL ? b2L + bz * sB : nullptr;

    // Per-thread fragment address constants (swizzle folded in; row&7 == lane&7
    // for every fragment because all row offsets are multiples of 8).
    const uint32_t aRowB = (uint32_t)((wm * 64 + (lane & 15)) * 128);
    const uint32_t bRowB = (uint32_t)((wn * 32 + ((lane >> 4) << 3) + (lane & 7)) * 128);
    uint32_t gA16[2], gB16[2];
#pragma unroll
    for (int ks = 0; ks < 2; ++ks) {
        gA16[ks] = (uint32_t)(((ks * 2 + (lane >> 4)) ^ (lane & 7)) * 16);
        gB16[ks] = (uint32_t)(((ks * 2 + ((lane >> 3) & 1)) ^ (lane & 7)) * 16);
    }

    // prologue: chunks 0,1 -> stages 0,1  (all our GEMMs have nchunk >= 16)
    load_chunk(smem,           AH0, AL0, BH0, BL0, rowA, colB, lda, ldb, 0,  tid);
    load_chunk(smem + STAGE_B, AH0, AL0, BH0, BL0, rowA, colB, lda, ldb, BK, tid);

    for (int c = 0; c < nchunk; ++c) {
        if (c + 1 < nchunk)
            asm volatile("cp.async.wait_group 1;" ::: "memory");
        else
            asm volatile("cp.async.wait_group 0;" ::: "memory");
        __syncthreads();   // stage c%3 ready; all warps done computing c-1

        if (c + 2 < nchunk) {
            int cn = c + 2;
            int p  = cn / npc;
            int k0 = (cn % npc) * BK;
            uint32_t dst = smem + (uint32_t)((cn % NSTAGE) * STAGE_B);
            if (!DUAL || p == 0)
                load_chunk(dst, AH0, AL0, BH0, BL0, rowA, colB, lda, ldb, k0, tid);
            else
                load_chunk(dst, AH1, AL1, BH1, BL1, rowA, colB, lda, ldb, k0, tid);
        }

        const uint32_t sA_ = smem + (uint32_t)((c % NSTAGE) * STAGE_B);
        const uint32_t sB_ = sA_ + TILE_B;

#pragma unroll
        for (int ks = 0; ks < 2; ++ks) {
            uint32_t bhf[4][2], blf[4][2];
#pragma unroll
            for (int np = 0; np < 2; ++np) {   // 2 n-frag pairs per x4
                uint32_t boff = bRowB + (uint32_t)(np * 16 * 128);
                ldsm_x4(sB_ + boff + gB16[ks], bhf[2 * np][0], bhf[2 * np][1],
                                               bhf[2 * np + 1][0], bhf[2 * np + 1][1]);
                ldsm_x4(sB_ + (boff + gB16[ks] ^ 64u), blf[2 * np][0], blf[2 * np][1],
                                               blf[2 * np + 1][0], blf[2 * np + 1][1]);
            }
#pragma unroll
            for (int mf = 0; mf < 4; ++mf) {
                uint32_t aoff = aRowB + (uint32_t)(mf * 16 * 128);
                uint32_t ahf[4], alf[4];
                ldsm_x4(sA_ + aoff + gA16[ks], ahf[0], ahf[1], ahf[2], ahf[3]);
                ldsm_x4(sA_ + (aoff + gA16[ks] ^ 64u), alf[0], alf[1], alf[2], alf[3]);
#pragma unroll
                for (int nf = 0; nf < 4; ++nf) {
                    mma16816(acc[mf][nf], ahf, bhf[nf]);  // hi*hi
                    mma16816(acc[mf][nf], ahf, blf[nf]);  // hi*lo
                    mma16816(acc[mf][nf], alf, bhf[nf]);  // lo*hi
                }
            }
        }
    }

    // Epilogue: c0,c1 -> (row=rq, col=cq..cq+1); c2,c3 -> row+8.
    const int rq = lane >> 2, cq = (lane & 3) * 2;

#pragma unroll
    for (int mf = 0; mf < 4; ++mf) {
#pragma unroll
        for (int nf = 0; nf < 4; ++nf) {
            long col = colB + wn * 32 + nf * 8 + cq;
#pragma unroll
            for (int half = 0; half < 2; ++half) {
                long row = rowA + wm * 64 + mf * 16 + rq + half * 8;
                float v0 = acc[mf][nf][half * 2 + 0];
                float v1 = acc[mf][nf][half * 2 + 1];
                if (OUTF32) {
                    float* CF = cF + (long)bz * sC;
                    *(float2*)(CF + row * (long)ldc + col) = make_float2(v0, v1);
                } else {
                    if (TANH) { v0 = tanhf(v0); v1 = tanhf(v1); }
                    __nv_bfloat16 h0 = __float2bfloat16_rn(v0);
                    __nv_bfloat16 h1 = __float2bfloat16_rn(v1);
                    __nv_bfloat16 l0 = __float2bfloat16_rn(v0 - __bfloat162float(h0));
                    __nv_bfloat16 l1 = __float2bfloat16_rn(v1 - __bfloat162float(h1));
                    __nv_bfloat162 hp; hp.x = h0; hp.y = h1;
                    __nv_bfloat162 lp; lp.x = l0; lp.y = l1;
                    __nv_bfloat16* CH = cH + (long)bz * sC;
                    __nv_bfloat16* CL = cL + (long)bz * sC;
                    *(__nv_bfloat162*)(CH + row * (long)ldc + col) = hp;
                    *(__nv_bfloat162*)(CL + row * (long)ldc + col) = lp;
                }
            }
        }
    }
}

// ---------------------------------------------------------------------------
// fp32 -> (hi, lo) bf16 split, 4 elems/thread
// ---------------------------------------------------------------------------
__device__ __forceinline__ void split4(float4 v, uint2& uh, uint2& ul)
{
    float f[4] = {v.x, v.y, v.z, v.w};
    __nv_bfloat16 h[4], l[4];
#pragma unroll
    for (int j = 0; j < 4; ++j) {
        h[j] = __float2bfloat16_rn(f[j]);
        l[j] = __float2bfloat16_rn(f[j] - __bfloat162float(h[j]));
    }
    __nv_bfloat162 h01, h23, l01, l23;
    h01.x = h[0]; h01.y = h[1]; h23.x = h[2]; h23.y = h[3];
    l01.x = l[0]; l01.y = l[1]; l23.x = l[2]; l23.y = l[3];
    uh.x = *(uint32_t*)&h01; uh.y = *(uint32_t*)&h23;
    ul.x = *(uint32_t*)&l01; ul.y = *(uint32_t*)&l23;
}

__global__ void __launch_bounds__(256)
split_kernel(const float4* __restrict__ x, uint2* __restrict__ hi, uint2* __restrict__ lo)
{
    long i = (long)blockIdx.x * blockDim.x + threadIdx.x;
    uint2 uh, ul;
    split4(x[i], uh, ul);
    hi[i] = uh; lo[i] = ul;
}

// Fused weight split: W1 (65536 f4) | Wout1 (131072 f4) | W2 (65536 f4)
__global__ void __launch_bounds__(256)
wsplit_kernel(const float4* __restrict__ w1, const float4* __restrict__ wo1,
              const float4* __restrict__ w2,
              uint2* __restrict__ w1h, uint2* __restrict__ w1l,
              uint2* __restrict__ wo1h, uint2* __restrict__ wo1l,
              uint2* __restrict__ w2h, uint2* __restrict__ w2l)
{
    long i = (long)blockIdx.x * blockDim.x + threadIdx.x;
    const float4* src; uint2 *dh, *dl; long j;
    if (i < 65536)       { src = w1;  dh = w1h;  dl = w1l;  j = i; }
    else if (i < 196608) { src = wo1; dh = wo1h; dl = wo1l; j = i - 65536; }
    else                 { src = w2;  dh = w2h;  dl = w2l;  j = i - 196608; }
    uint2 uh, ul;
    split4(src[j], uh, ul);
    dh[j] = uh; dl[j] = ul;
}

// ---------------------------------------------------------------------------
// Per-batch 512x512 bf16 transpose; z in [0,512): z<256 -> hi arrays, else lo.
// ---------------------------------------------------------------------------
__global__ void __launch_bounds__(256)
transpose2_bf16(const __nv_bfloat16* __restrict__ in_h, __nv_bfloat16* __restrict__ out_h,
                const __nv_bfloat16* __restrict__ in_l, __nv_bfloat16* __restrict__ out_l)
{
    __shared__ __nv_bfloat16 tile[32][33];
    const int z = blockIdx.z;
    const bool lo = z >= 256;
    const __nv_bfloat16* in  = lo ? in_l  : in_h;
    __nv_bfloat16*       out = lo ? out_l : out_h;
    const long base = (long)(z & 255) * 262144;
    int x = blockIdx.x * 32 + threadIdx.x;
    int y0 = blockIdx.y * 32;
#pragma unroll
    for (int j = 0; j < 32; j += 8)
        tile[threadIdx.y + j][threadIdx.x] = in[base + (long)(y0 + threadIdx.y + j) * 512 + x];
    __syncthreads();
    int xo = blockIdx.y * 32 + threadIdx.x;
    int yo0 = blockIdx.x * 32;
#pragma unroll
    for (int j = 0; j < 32; j += 8)
        out[base + (long)(yo0 + threadIdx.y + j) * 512 + xo] = tile[threadIdx.x][threadIdx.y + j];
}

// ---------------------------------------------------------------------------
// Row softmax over 512: fp32 in, hi/lo bf16 out. 128 thr/row.
// ---------------------------------------------------------------------------
__global__ void __launch_bounds__(128)
softmax512_f32(const float* __restrict__ S,
               __nv_bfloat16* __restrict__ PH, __nv_bfloat16* __restrict__ PL)
{
    __shared__ float redm[4], reds[4];
    const long row = blockIdx.x;
    const int t = threadIdx.x;

    float4 vv = ((const float4*)(S + row * 512))[t];
    float v[4] = {vv.x, vv.y, vv.z, vv.w};

    float m = fmaxf(fmaxf(v[0], v[1]), fmaxf(v[2], v[3]));
#pragma unroll
    for (int o = 16; o; o >>= 1) m = fmaxf(m, __shfl_xor_sync(0xffffffffu, m, o));
    if ((t & 31) == 0) redm[t >> 5] = m;
    __syncthreads();
    m = fmaxf(fmaxf(redm[0], redm[1]), fmaxf(redm[2], redm[3]));

    float s = 0.f;
#pragma unroll
    for (int j = 0; j < 4; ++j) { v[j] = __expf(v[j] - m); s += v[j]; }
#pragma unroll
    for (int o = 16; o; o >>= 1) s += __shfl_xor_sync(0xffffffffu, s, o);
    if ((t & 31) == 0) reds[t >> 5] = s;
    __syncthreads();
    s = reds[0] + reds[1] + reds[2] + reds[3];
    float r = 1.0f / s;

    float4 w = make_float4(v[0] * r, v[1] * r, v[2] * r, v[3] * r);
    uint2 uh, ul;
    split4(w, uh, ul);
    ((uint2*)(PH + row * 512))[t] = uh;
    ((uint2*)(PL + row * 512))[t] = ul;
}

// ---------------------------------------------------------------------------
// out[b,j] = (1/512) * sum_i (hi+lo)[b,i,j]
// ---------------------------------------------------------------------------
__global__ void __launch_bounds__(512)
meanrows_kernel(const __nv_bfloat16* __restrict__ hi, const __nv_bfloat16* __restrict__ lo,
                float* __restrict__ out)
{
    const long base = (long)blockIdx.x * 262144 + threadIdx.x;
    float s = 0.f;
#pragma unroll 4
    for (int i = 0; i < 512; ++i) {
        long off = base + (long)i * 512;
        s += __bfloat162float(hi[off]) + __bfloat162float(lo[off]);
    }
    out[blockIdx.x * 512 + threadIdx.x] = s * (1.0f / 512.0f);
}

// ---------------------------------------------------------------------------
// mixbar[b,d] = sum_m pbar[b,m] * (hi+lo)(h[b,m,d])
// ---------------------------------------------------------------------------
__global__ void __launch_bounds__(512)
mixbar_kernel(const float* __restrict__ pbar,
              const __nv_bfloat16* __restrict__ hh, const __nv_bfloat16* __restrict__ hl,
              float* __restrict__ mbar)
{
    __shared__ float pb[512];
    const int b = blockIdx.x, d = threadIdx.x;
    pb[d] = pbar[b * 512 + d];
    __syncthreads();
    const long base = (long)b * 262144 + d;
    float s = 0.f;
#pragma unroll 4
    for (int m = 0; m < 512; ++m) {
        long off = base + (long)m * 512;
        s += pb[m] * (__bfloat162float(hh[off]) + __bfloat162float(hl[off]));
    }
    mbar[b * 512 + d] = s;
}

// ---------------------------------------------------------------------------
// out[b,d] = sum_c mixbar[b,c]*W[d,c] + sum_c qbar[b,c]*W[d,512+c]   (W: [512,1024])
// ---------------------------------------------------------------------------
__global__ void __launch_bounds__(512)
final_kernel(const float* __restrict__ mixbar, const float* __restrict__ qbar,
             const float* __restrict__ W, float* __restrict__ out)
{
    __shared__ float mb[512], qb[512];
    const int b = blockIdx.x, d = threadIdx.x;
    mb[d] = mixbar[b * 512 + d];
    qb[d] = qbar[b * 512 + d];
    __syncthreads();
    const float4* w4 = (const float4*)(W + (long)d * 1024);
    float s = 0.f;
#pragma unroll 4
    for (int c4 = 0; c4 < 128; ++c4) {
        float4 w = w4[c4];
        int c = c4 * 4;
        s += mb[c] * w.x + mb[c + 1] * w.y + mb[c + 2] * w.z + mb[c + 3] * w.w;
    }
#pragma unroll 4
    for (int c4 = 128; c4 < 256; ++c4) {
        float4 w = w4[c4];
        int c = c4 * 4 - 512;
        s += qb[c] * w.x + qb[c + 1] * w.y + qb[c + 2] * w.z + qb[c + 3] * w.w;
    }
    out[b * 512 + d] = s;
}

// ---------------------------------------------------------------------------

extern "C" void kernel_launch(void* const* d_in, const int* in_sizes, int n_in,
                              void* d_out, int out_size)
{
    const float* x     = (const float*)d_in[0];
    const float* Win1  = (const float*)d_in[1];
    const float* Wout1 = (const float*)d_in[2];
    const float* Win2  = (const float*)d_in[3];
    const float* Wout2 = (const float*)d_in[4];
    float* out = (float*)d_out;

    __nv_bfloat16 *xh, *xl, *xth, *xtl, *qh, *ql, *sh, *sl, *mh, *ml;
    __nv_bfloat16 *w1h, *w1l, *wo1h, *wo1l, *w2h, *w2l;
    float *sf, *pbar, *qbar, *mbar2;
    cudaGetSymbolAddress((void**)&xh,  g_xh);   cudaGetSymbolAddress((void**)&xl,  g_xl);
    cudaGetSymbolAddress((void**)&xth, g_xth);  cudaGetSymbolAddress((void**)&xtl, g_xtl);
    cudaGetSymbolAddress((void**)&qh,  g_qh);   cudaGetSymbolAddress((void**)&ql,  g_ql);
    cudaGetSymbolAddress((void**)&sh,  g_sh);   cudaGetSymbolAddress((void**)&sl,  g_sl);
    cudaGetSymbolAddress((void**)&mh,  g_mh);   cudaGetSymbolAddress((void**)&ml,  g_ml);
    cudaGetSymbolAddress((void**)&sf,  g_sf);
    cudaGetSymbolAddress((void**)&w1h, g_w1h);  cudaGetSymbolAddress((void**)&w1l, g_w1l);
    cudaGetSymbolAddress((void**)&wo1h,g_wo1h); cudaGetSymbolAddress((void**)&wo1l,g_wo1l);
    cudaGetSymbolAddress((void**)&w2h, g_w2h);  cudaGetSymbolAddress((void**)&w2l, g_w2l);
    cudaGetSymbolAddress((void**)&pbar, g_pbar);
    cudaGetSymbolAddress((void**)&qbar, g_qbar);
    cudaGetSymbolAddress((void**)&mbar2, g_mbar2);

    cudaFuncSetAttribute(gemm_hmma<false, false, false>,
                         cudaFuncAttributeMaxDynamicSharedMemorySize, GEMM_DYN_SMEM);
    cudaFuncSetAttribute(gemm_hmma<false, false, true>,
                         cudaFuncAttributeMaxDynamicSharedMemorySize, GEMM_DYN_SMEM);
    cudaFuncSetAttribute(gemm_hmma<true, true, false>,
                         cudaFuncAttributeMaxDynamicSharedMemorySize, GEMM_DYN_SMEM);

    const int  M_FLAT = BATCH * SEQ;     // 131072
    const long LDb = 262144;

    // ---- splits + fused transpose ----
    wsplit_kernel<<<262144 / 256, 256>>>(
        (const float4*)Win1, (const float4*)Wout1, (const float4*)Win2,
        (uint2*)w1h, (uint2*)w1l, (uint2*)wo1h, (uint2*)wo1l, (uint2*)w2h, (uint2*)w2l);
    split_kernel<<<(int)(NEL / 4 / 256), 256>>>((const float4*)x, (uint2*)xh, (uint2*)xl);
    transpose2_bf16<<<dim3(16, 16, 512), dim3(32, 8)>>>(xh, xth, xl, xtl);

    // ---- block 1 ----
    // q1 = X @ Win1^T
    gemm_hmma<false, false, false><<<dim3(4, 1024, 1), 256, GEMM_DYN_SMEM>>>(
        xh, xl, 512, 0, w1h, w1l, 512, 0,
        nullptr, nullptr, nullptr, nullptr, qh, ql, nullptr, 512, 0, 512);
    // S1[b] = q1[b] @ X[b]^T  (fp32 out)
    gemm_hmma<false, false, true><<<dim3(4, 4, 256), 256, GEMM_DYN_SMEM>>>(
        qh, ql, 512, LDb, xh, xl, 512, LDb,
        nullptr, nullptr, nullptr, nullptr, nullptr, nullptr, sf, 512, LDb, 512);
    softmax512_f32<<<M_FLAT, 128>>>(sf, sh, sl);
    // mix1[b] = P1[b] @ X[b]   (B = X^T, K-major over m)
    gemm_hmma<false, false, false><<<dim3(4, 4, 256), 256, GEMM_DYN_SMEM>>>(
        sh, sl, 512, LDb, xth, xtl, 512, LDb,
        nullptr, nullptr, nullptr, nullptr, mh, ml, nullptr, 512, LDb, 512);
    // h = tanh(mix1 @ Wout1[:, :512]^T + q1 @ Wout1[:, 512:]^T) -> overwrite X slots
    gemm_hmma<true, true, false><<<dim3(4, 1024, 1), 256, GEMM_DYN_SMEM>>>(
        mh, ml, 512, 0, wo1h, wo1l, 1024, 0,
        qh, ql, wo1h + 512, wo1l + 512, xh, xl, nullptr, 512, 0, 512);

    // ---- block 2 (pooling collapsed: no mix2 / out-proj GEMMs) ----
    // q2 = h @ Win2^T
    gemm_hmma<false, false, false><<<dim3(4, 1024, 1), 256, GEMM_DYN_SMEM>>>(
        xh, xl, 512, 0, w2h, w2l, 512, 0,
        nullptr, nullptr, nullptr, nullptr, qh, ql, nullptr, 512, 0, 512);
    // S2[b] = q2[b] @ h[b]^T  (fp32 out)
    gemm_hmma<false, false, true><<<dim3(4, 4, 256), 256, GEMM_DYN_SMEM>>>(
        qh, ql, 512, LDb, xh, xl, 512, LDb,
        nullptr, nullptr, nullptr, nullptr, nullptr, nullptr, sf, 512, LDb, 512);
    softmax512_f32<<<M_FLAT, 128>>>(sf, sh, sl);

    meanrows_kernel<<<BATCH, 512>>>(sh, sl, pbar);   // pbar[b,m] = mean_l P2
    meanrows_kernel<<<BATCH, 512>>>(qh, ql, qbar);   // qbar[b,d] = mean_l q2
    mixbar_kernel<<<BATCH, 512>>>(pbar, xh, xl, mbar2);
    final_kernel<<<BATCH, 512>>>(mbar2, qbar, Wout2, out);
}